// round 12
// baseline (speedup 1.0000x reference)
#include <cuda_runtime.h>
#include <cuda_bf16.h>
#include <cuda_fp16.h>
#include <math.h>
#include <stdint.h>

// Problem constants
#define BB 2
#define SS 2048
#define DIM 2048
#define NH 16
#define KVH 4
#define DH 128
#define MROWS (BB * SS)   // 4096
#define NQKV 3072         // fused QKV output width (2048 q + 512 k + 512 v)

// ---------------- scratch (device globals; no allocation allowed) -------------
// attention operands (fp16), layout [b,h,s,d]
__device__ __half g_q16[BB * NH * SS * DH];     // Q (scale folded)
__device__ __half g_k16[BB * KVH * SS * DH];    // K
__device__ __half g_v16[BB * KVH * SS * DH];    // V

// fp16 GEMM operands
__device__ __half g_x16[MROWS * DIM];           // x
__device__ __half g_wqkv16[NQKV * DIM];         // fused W_qkv, transposed [N][K]
__device__ __half g_wo16[DIM * DIM];            // W_o, transposed [N][K]
__device__ __half g_att16[MROWS * (NH*DH)];     // attention output

// rope tables [s][i], fp32 (computed in double)
__device__ float g_cs[SS * 64];
__device__ float g_sn[SS * 64];

// ---------------- PTX helpers ---------------------------------------------------
__device__ __forceinline__ uint32_t smem_u32(const void* p) {
    uint32_t a;
    asm("{ .reg .u64 t; cvta.to.shared.u64 t, %1; cvt.u32.u64 %0, t; }"
        : "=r"(a) : "l"(p));
    return a;
}

__device__ __forceinline__ void cp16(uint32_t dst, const void* src) {
    asm volatile("cp.async.cg.shared.global [%0], [%1], 16;\n"
                 :: "r"(dst), "l"(src));
}

__device__ __forceinline__ void ldm_x4(uint32_t r[4], uint32_t addr) {
    asm volatile("ldmatrix.sync.aligned.m8n8.x4.shared.b16 {%0,%1,%2,%3}, [%4];"
                 : "=r"(r[0]), "=r"(r[1]), "=r"(r[2]), "=r"(r[3]) : "r"(addr));
}

__device__ __forceinline__ void ldm_x4_t(uint32_t r[4], uint32_t addr) {
    asm volatile("ldmatrix.sync.aligned.m8n8.x4.trans.shared.b16 {%0,%1,%2,%3}, [%4];"
                 : "=r"(r[0]), "=r"(r[1]), "=r"(r[2]), "=r"(r[3]) : "r"(addr));
}

__device__ __forceinline__ void mma_f16(float c[4], const uint32_t a[4],
                                        uint32_t b0, uint32_t b1) {
    asm volatile(
        "mma.sync.aligned.m16n8k16.row.col.f32.f16.f16.f32 "
        "{%0,%1,%2,%3}, {%4,%5,%6,%7}, {%8,%9}, {%0,%1,%2,%3};"
        : "+f"(c[0]), "+f"(c[1]), "+f"(c[2]), "+f"(c[3])
        : "r"(a[0]), "r"(a[1]), "r"(a[2]), "r"(a[3]), "r"(b0), "r"(b1));
}

// ---------------- rope tables (double precision, matches jax fp32) --------------
__global__ void tab_kernel(const int* __restrict__ pos_ids)
{
    const int i = threadIdx.x;   // 0..63
    const int s = blockIdx.x;
    double invf = exp(-((double)(2 * i) / (double)DH) * log(10000.0));
    double ang = (double)pos_ids[s] * invf;
    g_cs[s * 64 + i] = (float)cos(ang);
    g_sn[s * 64 + i] = (float)sin(ang);
}

// ---------------- fp32 -> fp16 single convert ----------------------------------
__global__ __launch_bounds__(256) void cvt16_kernel(
    const float* __restrict__ in, __half* __restrict__ out, int n4)
{
    int i = blockIdx.x * blockDim.x + threadIdx.x;
    if (i >= n4) return;
    float4 v = ((const float4*)in)[i];
    __half2 a = __floats2half2_rn(v.x, v.y);
    __half2 b = __floats2half2_rn(v.z, v.w);
    ((__half2*)out)[2*i]   = a;
    ((__half2*)out)[2*i+1] = b;
}

// ---------------- fp32 [K][N] -> fp16 transposed [N][K] -------------------------
__global__ __launch_bounds__(256) void cvtT16_kernel(
    const float* __restrict__ W, __half* __restrict__ T, int K, int N)
{
    __shared__ float t[32][33];
    const int n0 = blockIdx.x * 32, k0 = blockIdx.y * 32;
    const int tx = threadIdx.x, ty = threadIdx.y;   // (32, 8)
    for (int i = ty; i < 32; i += 8)
        t[i][tx] = W[(size_t)(k0 + i) * N + n0 + tx];
    __syncthreads();
    for (int i = ty; i < 32; i += 8)
        T[(size_t)(n0 + i) * K + k0 + tx] = __float2half_rn(t[tx][i]);
}

// ---------------- fp16 GEMM core (shared mainloop) ------------------------------
#define GK 2048
#define ROWB 80
#define TILE_B (128 * ROWB)
#define OFF_A  0
#define OFF_B  (1 * TILE_B)
#define STG (2 * TILE_B)
#define TS_STRIDE 132
#define MM_SMEM (2 * STG)                      // 40960 (Wo GEMM)
#define MMQ_SMEM (128 * TS_STRIDE * 4)         // 67584 (QKV GEMM, epilogue tile)

// mainloop producing acc[4][8][4]; identical for both GEMM kernels
#define MM_MAINLOOP(A, B)                                                         \
    const uint32_t sb = smem_u32(smem);                                           \
    const int tid = threadIdx.x;                                                  \
    const int lane = tid & 31, warp = tid >> 5;                                   \
    const int m0 = blockIdx.y * 128, n0 = blockIdx.x * 128;                       \
    const int wm0 = (warp >> 1) * 64;                                             \
    const int wn0 = (warp & 1) * 64;                                              \
    const int arow_l  = lane & 15;                                                \
    const int akoff_l = (lane >> 4) << 3;                                         \
    const int brow_l  = (lane & 7) + ((lane >> 4) << 3);                          \
    const int bkoff_l = ((lane >> 3) & 1) << 3;                                   \
    float acc[4][8][4];                                                           \
    _Pragma("unroll")                                                             \
    for (int im = 0; im < 4; im++)                                                \
        _Pragma("unroll")                                                         \
        for (int j = 0; j < 8; j++)                                               \
            _Pragma("unroll")                                                     \
            for (int c = 0; c < 4; c++) acc[im][j][c] = 0.0f;                     \
    const int NT = GK / 32;                                                       \
    auto issue = [&](int t) {                                                     \
        const int k0 = t * 32;                                                    \
        const uint32_t sbase = sb + (t & 1) * STG;                                \
        _Pragma("unroll")                                                         \
        for (int i = 0; i < 4; i++) {                                             \
            const int c = tid + (i << 7);                                         \
            const int row = c >> 2;                                               \
            const int off = (c & 3) << 3;                                         \
            const uint32_t soff = (uint32_t)row * ROWB + ((uint32_t)off << 1);    \
            cp16(sbase + OFF_A + soff, A + (size_t)(m0 + row) * GK + k0 + off);   \
            cp16(sbase + OFF_B + soff, B + (size_t)(n0 + row) * GK + k0 + off);   \
        }                                                                         \
        asm volatile("cp.async.commit_group;");                                   \
    };                                                                            \
    issue(0);                                                                     \
    for (int t = 0; t < NT; t++) {                                                \
        if (t + 1 < NT) issue(t + 1);                                             \
        if (t + 1 < NT) { asm volatile("cp.async.wait_group 1;"); }               \
        else            { asm volatile("cp.async.wait_group 0;"); }               \
        __syncthreads();                                                          \
        const uint32_t sbase = sb + (t & 1) * STG;                                \
        _Pragma("unroll")                                                         \
        for (int ks = 0; ks < 2; ks++) {                                          \
            uint32_t ah[4][4];                                                    \
            const uint32_t kba = (uint32_t)(ks * 16 + akoff_l) << 1;              \
            _Pragma("unroll")                                                     \
            for (int im = 0; im < 4; im++) {                                      \
                uint32_t ra = sbase + (uint32_t)(wm0 + im * 16 + arow_l) * ROWB + kba; \
                ldm_x4(ah[im], ra + OFF_A);                                       \
            }                                                                     \
            const uint32_t kbb = (uint32_t)(ks * 16 + bkoff_l) << 1;              \
            _Pragma("unroll")                                                     \
            for (int np = 0; np < 4; np++) {                                      \
                uint32_t rb = sbase + (uint32_t)(wn0 + np * 16 + brow_l) * ROWB + kbb; \
                uint32_t bh[4];                                                   \
                ldm_x4(bh, rb + OFF_B);                                           \
                _Pragma("unroll")                                                 \
                for (int im = 0; im < 4; im++) {                                  \
                    _Pragma("unroll")                                             \
                    for (int ia = 0; ia < 2; ia++)                                \
                        mma_f16(acc[im][np * 2 + ia], ah[im],                     \
                                bh[2 * ia], bh[2 * ia + 1]);                      \
                }                                                                 \
            }                                                                     \
        }                                                                         \
        __syncthreads();                                                          \
    }

// ---------------- QKV GEMM with fused RoPE epilogue -----------------------------
__global__ __launch_bounds__(128) void mm_qkv_rope_kernel(
    const __half* __restrict__ A, const __half* __restrict__ B)
{
    extern __shared__ char smem[];
    MM_MAINLOOP(A, B)

    // ---- stage fp32 tile to smem -----------------------------------------------
    float* ts = (float*)smem;
#pragma unroll
    for (int im = 0; im < 4; im++) {
        int r = wm0 + im * 16 + (lane >> 2);
#pragma unroll
        for (int j = 0; j < 8; j++) {
            int cc = wn0 + j * 8 + (lane & 3) * 2;
            ts[r * TS_STRIDE + cc]           = acc[im][j][0];
            ts[r * TS_STRIDE + cc + 1]       = acc[im][j][1];
            ts[(r + 8) * TS_STRIDE + cc]     = acc[im][j][2];
            ts[(r + 8) * TS_STRIDE + cc + 1] = acc[im][j][3];
        }
    }
    __syncthreads();

    const float qk_scale = 0.08838834764831845f;   // 1/sqrt(128)
    const int i0 = lane * 2;                       // 0..62, pair columns (i0, i0+1)

    if (n0 < 2048) {
        // Q head: rope + scale
        const int h = n0 >> 7;
        for (int rr = warp; rr < 128; rr += 4) {
            int m = m0 + rr, b = m >> 11, s = m & (SS - 1);
            size_t dst = ((size_t)(b * NH + h) * SS + s) * DH;
            float c0 = g_cs[s * 64 + i0],  c1 = g_cs[s * 64 + i0 + 1];
            float s0 = g_sn[s * 64 + i0],  s1 = g_sn[s * 64 + i0 + 1];
            float x1a = ts[rr * TS_STRIDE + i0],      x1b = ts[rr * TS_STRIDE + i0 + 1];
            float x2a = ts[rr * TS_STRIDE + i0 + 64], x2b = ts[rr * TS_STRIDE + i0 + 65];
            __half2 lo = __floats2half2_rn((x1a * c0 - x2a * s0) * qk_scale,
                                           (x1b * c1 - x2b * s1) * qk_scale);
            __half2 hi = __floats2half2_rn((x2a * c0 + x1a * s0) * qk_scale,
                                           (x2b * c1 + x1b * s1) * qk_scale);
            *(__half2*)(g_q16 + dst + i0)      = lo;
            *(__half2*)(g_q16 + dst + 64 + i0) = hi;
        }
    } else if (n0 < 2560) {
        // K head: rope, no scale
        const int h = (n0 - 2048) >> 7;
        for (int rr = warp; rr < 128; rr += 4) {
            int m = m0 + rr, b = m >> 11, s = m & (SS - 1);
            size_t dst = ((size_t)(b * KVH + h) * SS + s) * DH;
            float c0 = g_cs[s * 64 + i0],  c1 = g_cs[s * 64 + i0 + 1];
            float s0 = g_sn[s * 64 + i0],  s1 = g_sn[s * 64 + i0 + 1];
            float x1a = ts[rr * TS_STRIDE + i0],      x1b = ts[rr * TS_STRIDE + i0 + 1];
            float x2a = ts[rr * TS_STRIDE + i0 + 64], x2b = ts[rr * TS_STRIDE + i0 + 65];
            __half2 lo = __floats2half2_rn(x1a * c0 - x2a * s0, x1b * c1 - x2b * s1);
            __half2 hi = __floats2half2_rn(x2a * c0 + x1a * s0, x2b * c1 + x1b * s1);
            *(__half2*)(g_k16 + dst + i0)      = lo;
            *(__half2*)(g_k16 + dst + 64 + i0) = hi;
        }
    } else {
        // V head: plain convert
        const int h = (n0 - 2560) >> 7;
        for (int rr = warp; rr < 128; rr += 4) {
            int m = m0 + rr, b = m >> 11, s = m & (SS - 1);
            size_t dst = ((size_t)(b * KVH + h) * SS + s) * DH;
            int c4 = lane * 4;
            __half2 v0 = __floats2half2_rn(ts[rr * TS_STRIDE + c4],
                                           ts[rr * TS_STRIDE + c4 + 1]);
            __half2 v1 = __floats2half2_rn(ts[rr * TS_STRIDE + c4 + 2],
                                           ts[rr * TS_STRIDE + c4 + 3]);
            *(__half2*)(g_v16 + dst + c4)     = v0;
            *(__half2*)(g_v16 + dst + c4 + 2) = v1;
        }
    }
}

// ---------------- plain fp16 GEMM (Wo projection) -------------------------------
__global__ __launch_bounds__(128) void mm_f16_kernel(
    const __half* __restrict__ A, const __half* __restrict__ B,
    float* __restrict__ C, int N)
{
    extern __shared__ char smem[];
    MM_MAINLOOP(A, B)

#pragma unroll
    for (int im = 0; im < 4; im++) {
        const int rbase = m0 + wm0 + im * 16 + (lane >> 2);
#pragma unroll
        for (int j = 0; j < 8; j++) {
            const int col = n0 + wn0 + j * 8 + (lane & 3) * 2;
            float2 v0 = make_float2(acc[im][j][0], acc[im][j][1]);
            float2 v1 = make_float2(acc[im][j][2], acc[im][j][3]);
            *(float2*)(C + (size_t)rbase * N + col)       = v0;
            *(float2*)(C + (size_t)(rbase + 8) * N + col) = v1;
        }
    }
}

// ---------------- flash attention (fp16 mma.sync 1-pass, causal, GQA) -----------
#define AQM 128
#define AKN 64
#define KROW 272                  // smem row stride bytes (256 data + 16 pad)
#define TB (AKN * KROW)           // 17408
#define AT_SMEM (4 * TB)          // 69632: 2 stages x (K, V)

__global__ __launch_bounds__(256) void attn_kernel()
{
    extern __shared__ char smc[];
    const uint32_t sb = smem_u32(smc);
    const int tid = threadIdx.x, lane = tid & 31, warp = tid >> 5;
    const int qt = (int)gridDim.x - 1 - (int)blockIdx.x;   // heavy tiles first
    const int h = blockIdx.y, b = blockIdx.z, kvh = h >> 2;
    const int q0 = qt * AQM;
    const int wm = warp * 16;

    const char* qp = (const char*)(g_q16 + ((size_t)(b * NH + h) * SS + q0) * DH);
    const char* kp = (const char*)(g_k16 + (size_t)(b * KVH + kvh) * SS * DH);
    const char* vp = (const char*)(g_v16 + (size_t)(b * KVH + kvh) * SS * DH);

    // ---- stage Q (128x128 fp16) into smem, ldmatrix to registers --------------
    for (int i = tid; i < 128 * 16; i += 256) {
        int row = i >> 4, ch = (i & 15) << 4;
        cp16(sb + (uint32_t)row * KROW + ch, qp + row * 256 + ch);
    }
    asm volatile("cp.async.commit_group;");
    asm volatile("cp.async.wait_group 0;");
    __syncthreads();

    const int arow = lane & 15, akoff = (lane >> 4) << 3;
    uint32_t qf[8][4];
#pragma unroll
    for (int kc = 0; kc < 8; kc++) {
        uint32_t ra = sb + (uint32_t)(wm + arow) * KROW + ((uint32_t)(kc * 16 + akoff) << 1);
        ldm_x4(qf[kc], ra);
    }
    __syncthreads();   // staging area free for K/V now

    float oacc[16][4];
#pragma unroll
    for (int j = 0; j < 16; j++)
#pragma unroll
        for (int c = 0; c < 4; c++) oacc[j][c] = 0.0f;
    float mrun0 = -INFINITY, mrun1 = -INFINITY;
    float lrun0 = 0.0f, lrun1 = 0.0f;

    const int nblocks = 2 * (qt + 1);
    const int brow = (lane & 7) + ((lane >> 4) << 3);
    const int bkoff = ((lane >> 3) & 1) << 3;
    const int vrow = lane & 15, vcoff = (lane >> 4) << 3;

    auto issue = [&](int t) {
        const uint32_t base = sb + (uint32_t)(t & 1) * (2 * TB);
        const size_t g0 = (size_t)t * AKN * 256;
        for (int i = tid; i < AKN * 16; i += 256) {
            int row = i >> 4, ch = (i & 15) << 4;
            uint32_t soff = (uint32_t)row * KROW + ch;
            size_t goff = g0 + (size_t)row * 256 + ch;
            cp16(base + soff,      kp + goff);
            cp16(base + TB + soff, vp + goff);
        }
        asm volatile("cp.async.commit_group;");
    };

    issue(0);

    for (int t = 0; t < nblocks; t++) {
        if (t + 1 < nblocks) { issue(t + 1); asm volatile("cp.async.wait_group 1;"); }
        else                 { asm volatile("cp.async.wait_group 0;"); }
        __syncthreads();
        const uint32_t base = sb + (uint32_t)(t & 1) * (2 * TB);

        // ---- S = Q K^T (single-pass fp16) -------------------------------------
        float sacc[8][4];
#pragma unroll
        for (int j = 0; j < 8; j++)
#pragma unroll
            for (int c = 0; c < 4; c++) sacc[j][c] = 0.0f;

#pragma unroll
        for (int kc = 0; kc < 8; kc++) {
            const uint32_t kb = (uint32_t)(kc * 16 + bkoff) << 1;
#pragma unroll
            for (int np = 0; np < 4; np++) {
                uint32_t rb = base + (uint32_t)(np * 16 + brow) * KROW + kb;
                uint32_t bh4[4];
                ldm_x4(bh4, rb);
#pragma unroll
                for (int ia = 0; ia < 2; ia++)
                    mma_f16(sacc[np * 2 + ia], qf[kc], bh4[2 * ia], bh4[2 * ia + 1]);
            }
        }

        // ---- causal mask (warp-uniform skip when fully unmasked) --------------
        const int k0 = t * AKN;
        if (k0 + AKN - 1 > q0 + wm) {
            const int r0 = q0 + wm + (lane >> 2);
#pragma unroll
            for (int j = 0; j < 8; j++) {
                int cb = k0 + j * 8 + ((lane & 3) << 1);
                if (cb     > r0)     sacc[j][0] = -INFINITY;
                if (cb + 1 > r0)     sacc[j][1] = -INFINITY;
                if (cb     > r0 + 8) sacc[j][2] = -INFINITY;
                if (cb + 1 > r0 + 8) sacc[j][3] = -INFINITY;
            }
        }

        // ---- online softmax ---------------------------------------------------
        float mx0 = -INFINITY, mx1 = -INFINITY;
#pragma unroll
        for (int j = 0; j < 8; j++) {
            mx0 = fmaxf(mx0, fmaxf(sacc[j][0], sacc[j][1]));
            mx1 = fmaxf(mx1, fmaxf(sacc[j][2], sacc[j][3]));
        }
        mx0 = fmaxf(mx0, __shfl_xor_sync(0xffffffffu, mx0, 1));
        mx0 = fmaxf(mx0, __shfl_xor_sync(0xffffffffu, mx0, 2));
        mx1 = fmaxf(mx1, __shfl_xor_sync(0xffffffffu, mx1, 1));
        mx1 = fmaxf(mx1, __shfl_xor_sync(0xffffffffu, mx1, 2));
        float mn0 = fmaxf(mrun0, mx0), mn1 = fmaxf(mrun1, mx1);

        float sum0 = 0.0f, sum1 = 0.0f;
#pragma unroll
        for (int j = 0; j < 8; j++) {
            float e0 = __expf(sacc[j][0] - mn0);
            float e1 = __expf(sacc[j][1] - mn0);
            float e2 = __expf(sacc[j][2] - mn1);
            float e3 = __expf(sacc[j][3] - mn1);
            sacc[j][0] = e0; sacc[j][1] = e1; sacc[j][2] = e2; sacc[j][3] = e3;
            sum0 += e0 + e1; sum1 += e2 + e3;
        }
        sum0 += __shfl_xor_sync(0xffffffffu, sum0, 1);
        sum0 += __shfl_xor_sync(0xffffffffu, sum0, 2);
        sum1 += __shfl_xor_sync(0xffffffffu, sum1, 1);
        sum1 += __shfl_xor_sync(0xffffffffu, sum1, 2);

        float c0 = __expf(mrun0 - mn0), c1 = __expf(mrun1 - mn1);
        lrun0 = lrun0 * c0 + sum0;
        lrun1 = lrun1 * c1 + sum1;
        mrun0 = mn0; mrun1 = mn1;
#pragma unroll
        for (int j = 0; j < 16; j++) {
            oacc[j][0] *= c0; oacc[j][1] *= c0;
            oacc[j][2] *= c1; oacc[j][3] *= c1;
        }

        // ---- O += P V (single-pass fp16) --------------------------------------
#pragma unroll
        for (int kc = 0; kc < 4; kc++) {
            uint32_t pa[4];
            __half2 p0 = __floats2half2_rn(sacc[2*kc][0],   sacc[2*kc][1]);
            __half2 p1 = __floats2half2_rn(sacc[2*kc][2],   sacc[2*kc][3]);
            __half2 p2 = __floats2half2_rn(sacc[2*kc+1][0], sacc[2*kc+1][1]);
            __half2 p3 = __floats2half2_rn(sacc[2*kc+1][2], sacc[2*kc+1][3]);
            pa[0] = *(uint32_t*)&p0; pa[1] = *(uint32_t*)&p1;
            pa[2] = *(uint32_t*)&p2; pa[3] = *(uint32_t*)&p3;
#pragma unroll
            for (int nd = 0; nd < 8; nd++) {
                uint32_t rv = base + TB + (uint32_t)(kc * 16 + vrow) * KROW
                              + ((uint32_t)(nd * 16 + vcoff) << 1);
                uint32_t vh4[4];
                ldm_x4_t(vh4, rv);
#pragma unroll
                for (int ia = 0; ia < 2; ia++)
                    mma_f16(oacc[nd * 2 + ia], pa, vh4[2 * ia], vh4[2 * ia + 1]);
            }
        }
        __syncthreads();
    }

    // ---- epilogue: normalize, write single fp16 for the Wo GEMM ----------------
    const float inv0 = 1.0f / lrun0, inv1 = 1.0f / lrun1;
    const size_t r0 = (size_t)(b * SS + q0 + wm + (lane >> 2)) * (NH * DH)
                      + h * DH + ((lane & 3) << 1);
    const size_t r1 = r0 + (size_t)8 * (NH * DH);
#pragma unroll
    for (int nd = 0; nd < 16; nd++) {
        __half2 h0 = __floats2half2_rn(oacc[nd][0] * inv0, oacc[nd][1] * inv0);
        __half2 h1 = __floats2half2_rn(oacc[nd][2] * inv1, oacc[nd][3] * inv1);
        *(__half2*)(g_att16 + r0 + nd * 8) = h0;
        *(__half2*)(g_att16 + r1 + nd * 8) = h1;
    }
}

// ---------------- launch --------------------------------------------------------
extern "C" void kernel_launch(void* const* d_in, const int* in_sizes, int n_in,
                              void* d_out, int out_size)
{
    const float* x   = (const float*)d_in[0];
    // d_in[1] = mask (causal; handled analytically)
    const int*   pos = (const int*)d_in[2];
    const float* Wq  = (const float*)d_in[3];
    const float* Wk  = (const float*)d_in[4];
    const float* Wv  = (const float*)d_in[5];
    const float* Wo  = (const float*)d_in[6];
    float* out = (float*)d_out;

    __half *x16, *wqkv, *wo, *att16;
    cudaGetSymbolAddress((void**)&x16,   g_x16);
    cudaGetSymbolAddress((void**)&wqkv,  g_wqkv16);
    cudaGetSymbolAddress((void**)&wo,    g_wo16);
    cudaGetSymbolAddress((void**)&att16, g_att16);

    cudaFuncSetAttribute(attn_kernel,
                         cudaFuncAttributeMaxDynamicSharedMemorySize, AT_SMEM);
    cudaFuncSetAttribute(mm_f16_kernel,
                         cudaFuncAttributeMaxDynamicSharedMemorySize, MM_SMEM);
    cudaFuncSetAttribute(mm_qkv_rope_kernel,
                         cudaFuncAttributeMaxDynamicSharedMemorySize, MMQ_SMEM);

    // rope tables + operand conversion
    tab_kernel<<<SS, 64>>>(pos);
    cvt16_kernel<<<(MROWS * DIM / 4 + 255) / 256, 256>>>(x, x16, MROWS * DIM / 4);
    cvtT16_kernel<<<dim3(DIM / 32, DIM / 32), dim3(32, 8)>>>(Wq, wqkv, DIM, DIM);
    cvtT16_kernel<<<dim3((KVH * DH) / 32, DIM / 32), dim3(32, 8)>>>(
        Wk, wqkv + (size_t)2048 * DIM, DIM, KVH * DH);
    cvtT16_kernel<<<dim3((KVH * DH) / 32, DIM / 32), dim3(32, 8)>>>(
        Wv, wqkv + (size_t)2560 * DIM, DIM, KVH * DH);
    cvtT16_kernel<<<dim3(DIM / 32, DIM / 32), dim3(32, 8)>>>(Wo, wo, DIM, DIM);

    // fused QKV projection + RoPE epilogue (writes g_q16/g_k16/g_v16 directly)
    mm_qkv_rope_kernel<<<dim3(NQKV / 128, MROWS / 128), 128, MMQ_SMEM>>>(x16, wqkv);

    // attention on tensor cores (fp16 single-pass)
    attn_kernel<<<dim3(SS / AQM, NH, BB), 256, AT_SMEM>>>();

    // output projection (fp16 single-pass)
    mm_f16_kernel<<<dim3(DIM / 128, MROWS / 128), 128, MM_SMEM>>>(
        att16, wo, out, DIM);
}

// round 13
// speedup vs baseline: 1.0479x; 1.0479x over previous
#include <cuda_runtime.h>
#include <cuda_bf16.h>
#include <cuda_fp16.h>
#include <math.h>
#include <stdint.h>

// Problem constants
#define BB 2
#define SS 2048
#define DIM 2048
#define NH 16
#define KVH 4
#define DH 128
#define MROWS (BB * SS)   // 4096
#define NQKV 3072         // fused QKV output width (2048 q + 512 k + 512 v)

// ---------------- scratch (device globals; no allocation allowed) -------------
__device__ float g_qkvraw[MROWS * NQKV];        // fused QKV projection output

// attention operands (fp16), layout [b,h,s,d]
__device__ __half g_q16[BB * NH * SS * DH];     // Q (scale folded)
__device__ __half g_k16[BB * KVH * SS * DH];    // K
__device__ __half g_v16[BB * KVH * SS * DH];    // V

// fp16 GEMM operands
__device__ __half g_x16[MROWS * DIM];           // x
__device__ __half g_wqkv16[NQKV * DIM];         // fused W_qkv, transposed [N][K]
__device__ __half g_wo16[DIM * DIM];            // W_o, transposed [N][K]
__device__ __half g_att16[MROWS * (NH*DH)];     // attention output

// ---------------- PTX helpers ---------------------------------------------------
__device__ __forceinline__ uint32_t smem_u32(const void* p) {
    uint32_t a;
    asm("{ .reg .u64 t; cvta.to.shared.u64 t, %1; cvt.u32.u64 %0, t; }"
        : "=r"(a) : "l"(p));
    return a;
}

__device__ __forceinline__ void cp16(uint32_t dst, const void* src) {
    asm volatile("cp.async.cg.shared.global [%0], [%1], 16;\n"
                 :: "r"(dst), "l"(src));
}

__device__ __forceinline__ void ldm_x4(uint32_t r[4], uint32_t addr) {
    asm volatile("ldmatrix.sync.aligned.m8n8.x4.shared.b16 {%0,%1,%2,%3}, [%4];"
                 : "=r"(r[0]), "=r"(r[1]), "=r"(r[2]), "=r"(r[3]) : "r"(addr));
}

__device__ __forceinline__ void ldm_x4_t(uint32_t r[4], uint32_t addr) {
    asm volatile("ldmatrix.sync.aligned.m8n8.x4.trans.shared.b16 {%0,%1,%2,%3}, [%4];"
                 : "=r"(r[0]), "=r"(r[1]), "=r"(r[2]), "=r"(r[3]) : "r"(addr));
}

__device__ __forceinline__ void mma_f16(float c[4], const uint32_t a[4],
                                        uint32_t b0, uint32_t b1) {
    asm volatile(
        "mma.sync.aligned.m16n8k16.row.col.f32.f16.f16.f32 "
        "{%0,%1,%2,%3}, {%4,%5,%6,%7}, {%8,%9}, {%0,%1,%2,%3};"
        : "+f"(c[0]), "+f"(c[1]), "+f"(c[2]), "+f"(c[3])
        : "r"(a[0]), "r"(a[1]), "r"(a[2]), "r"(a[3]), "r"(b0), "r"(b1));
}

// ---------------- fp32 -> fp16 single convert ----------------------------------
__global__ __launch_bounds__(256) void cvt16_kernel(
    const float* __restrict__ in, __half* __restrict__ out, int n4)
{
    int i = blockIdx.x * blockDim.x + threadIdx.x;
    if (i >= n4) return;
    float4 v = ((const float4*)in)[i];
    __half2 a = __floats2half2_rn(v.x, v.y);
    __half2 b = __floats2half2_rn(v.z, v.w);
    ((__half2*)out)[2*i]   = a;
    ((__half2*)out)[2*i+1] = b;
}

// ---------------- all weights: fp32 [K][N] -> fp16 transposed [N][K], one launch -
__global__ __launch_bounds__(256) void cvtT16_all_kernel(
    const float* __restrict__ Wq, const float* __restrict__ Wk,
    const float* __restrict__ Wv, const float* __restrict__ Wo)
{
    const int z = blockIdx.z;
    const float* W;
    __half* T;
    int N;
    if (z == 0)      { W = Wq; T = g_wqkv16;                        N = DIM; }
    else if (z == 1) { W = Wk; T = g_wqkv16 + (size_t)2048 * DIM;   N = KVH * DH; }
    else if (z == 2) { W = Wv; T = g_wqkv16 + (size_t)2560 * DIM;   N = KVH * DH; }
    else             { W = Wo; T = g_wo16;                          N = DIM; }
    if (blockIdx.x * 32 >= N) return;

    __shared__ float t[32][33];
    const int n0 = blockIdx.x * 32, k0 = blockIdx.y * 32;
    const int tx = threadIdx.x, ty = threadIdx.y;   // (32, 8)
    for (int i = ty; i < 32; i += 8)
        t[i][tx] = W[(size_t)(k0 + i) * N + n0 + tx];
    __syncthreads();
    for (int i = ty; i < 32; i += 8)
        T[(size_t)(n0 + i) * DIM + k0 + tx] = __float2half_rn(t[tx][i]);
}

// ---------------- fp16 mma.sync single-pass GEMM --------------------------------
// C[M,N] = A @ B^T.  A:[M][K] fp16, B:[N][K] fp16.
// 4 warps, warp tile 64x64; CTA 128x128, BK=32, double-buffered cp.async.
#define GK 2048
#define ROWB 80
#define TILE_B (128 * ROWB)
#define OFF_A  0
#define OFF_B  (1 * TILE_B)
#define STG (2 * TILE_B)
#define MM_SMEM (2 * STG)   // 40960

__global__ __launch_bounds__(128) void mm_f16_kernel(
    const __half* __restrict__ A, const __half* __restrict__ B,
    float* __restrict__ C, int N)
{
    extern __shared__ char smem[];
    const uint32_t sb = smem_u32(smem);
    const int tid = threadIdx.x;
    const int lane = tid & 31, warp = tid >> 5;
    const int m0 = blockIdx.y * 128, n0 = blockIdx.x * 128;
    const int wm0 = (warp >> 1) * 64;
    const int wn0 = (warp & 1) * 64;

    const int arow_l  = lane & 15;
    const int akoff_l = (lane >> 4) << 3;
    const int brow_l  = (lane & 7) + ((lane >> 4) << 3);
    const int bkoff_l = ((lane >> 3) & 1) << 3;

    float acc[4][8][4];
#pragma unroll
    for (int im = 0; im < 4; im++)
#pragma unroll
        for (int j = 0; j < 8; j++)
#pragma unroll
            for (int c = 0; c < 4; c++) acc[im][j][c] = 0.0f;

    const int NT = GK / 32;

    auto issue = [&](int t) {
        const int k0 = t * 32;
        const uint32_t sbase = sb + (t & 1) * STG;
#pragma unroll
        for (int i = 0; i < 4; i++) {
            const int c = tid + (i << 7);
            const int row = c >> 2;
            const int off = (c & 3) << 3;
            const uint32_t soff = (uint32_t)row * ROWB + ((uint32_t)off << 1);
            cp16(sbase + OFF_A + soff, A + (size_t)(m0 + row) * GK + k0 + off);
            cp16(sbase + OFF_B + soff, B + (size_t)(n0 + row) * GK + k0 + off);
        }
        asm volatile("cp.async.commit_group;");
    };

    issue(0);

    for (int t = 0; t < NT; t++) {
        if (t + 1 < NT) issue(t + 1);
        if (t + 1 < NT) { asm volatile("cp.async.wait_group 1;"); }
        else            { asm volatile("cp.async.wait_group 0;"); }
        __syncthreads();

        const uint32_t sbase = sb + (t & 1) * STG;
#pragma unroll
        for (int ks = 0; ks < 2; ks++) {
            uint32_t ah[4][4];
            const uint32_t kba = (uint32_t)(ks * 16 + akoff_l) << 1;
#pragma unroll
            for (int im = 0; im < 4; im++) {
                uint32_t ra = sbase + (uint32_t)(wm0 + im * 16 + arow_l) * ROWB + kba;
                ldm_x4(ah[im], ra + OFF_A);
            }
            const uint32_t kbb = (uint32_t)(ks * 16 + bkoff_l) << 1;
#pragma unroll
            for (int np = 0; np < 4; np++) {
                uint32_t rb = sbase + (uint32_t)(wn0 + np * 16 + brow_l) * ROWB + kbb;
                uint32_t bh[4];
                ldm_x4(bh, rb + OFF_B);
#pragma unroll
                for (int im = 0; im < 4; im++) {
#pragma unroll
                    for (int ia = 0; ia < 2; ia++)
                        mma_f16(acc[im][np * 2 + ia], ah[im],
                                bh[2 * ia], bh[2 * ia + 1]);
                }
            }
        }
        __syncthreads();
    }

#pragma unroll
    for (int im = 0; im < 4; im++) {
        const int rbase = m0 + wm0 + im * 16 + (lane >> 2);
#pragma unroll
        for (int j = 0; j < 8; j++) {
            const int col = n0 + wn0 + j * 8 + (lane & 3) * 2;
            float2 v0 = make_float2(acc[im][j][0], acc[im][j][1]);
            float2 v1 = make_float2(acc[im][j][2], acc[im][j][3]);
            *(float2*)(C + (size_t)rbase * N + col)       = v0;
            *(float2*)(C + (size_t)(rbase + 8) * N + col) = v1;
        }
    }
}

// ---------------- RoPE -> fp16 attention operands [b,h,s,d] --------------------
__global__ __launch_bounds__(256) void rope_kernel(const int* __restrict__ pos_ids)
{
    const int s = blockIdx.x;
    const int b = blockIdx.y;
    const int t = threadIdx.x;

    __shared__ float cs[64], sn[64];
    if (t < 64) {
        double invf = exp(-((double)(2 * t) / (double)DH) * log(10000.0));
        double ang = (double)pos_ids[s] * invf;
        cs[t] = (float)cos(ang);
        sn[t] = (float)sin(ang);
    }
    __syncthreads();

    const float qk_scale = 0.08838834764831845f;   // 1/sqrt(128), folded into Q
    const float* row = g_qkvraw + (size_t)(b * SS + s) * NQKV;

    // Q: single fp16 (scale folded)
    for (int idx = t; idx < NH * 64; idx += 256) {
        int h = idx >> 6, i = idx & 63;
        float x1 = row[h * DH + i];
        float x2 = row[h * DH + 64 + i];
        size_t dst = ((size_t)(b * NH + h) * SS + s) * DH;
        g_q16[dst + i]      = __float2half_rn((x1 * cs[i] - x2 * sn[i]) * qk_scale);
        g_q16[dst + 64 + i] = __float2half_rn((x2 * cs[i] + x1 * sn[i]) * qk_scale);
    }

    // K: single fp16
    const float* krow = row + 2048;
    for (int idx = t; idx < KVH * 64; idx += 256) {
        int h = idx >> 6, i = idx & 63;
        float x1 = krow[h * DH + i];
        float x2 = krow[h * DH + 64 + i];
        size_t dst = ((size_t)(b * KVH + h) * SS + s) * DH;
        g_k16[dst + i]      = __float2half_rn(x1 * cs[i] - x2 * sn[i]);
        g_k16[dst + 64 + i] = __float2half_rn(x2 * cs[i] + x1 * sn[i]);
    }

    // V: single fp16
    const float* vrow = row + 2560;
    for (int idx = t; idx < KVH * DH; idx += 256) {
        int h = idx >> 7, d = idx & 127;
        g_v16[((size_t)(b * KVH + h) * SS + s) * DH + d] = __float2half_rn(vrow[idx]);
    }
}

// ---------------- flash attention (fp16 mma.sync, causal, GQA) ------------------
// CTA: 128 q rows x 128-key blocks. 8 warps x 16 q rows. 1 CTA/SM (reg-bound),
// so per-block fixed costs are exposed -> wide K-tile amortizes them.
#define AQM 128
#define AKN 128
#define KROW 272                  // smem row stride bytes (256 data + 16 pad)
#define TB (AKN * KROW)           // 34816
#define AT_SMEM (4 * TB)          // 139264: 2 stages x (K, V)

__global__ __launch_bounds__(256) void attn_kernel()
{
    extern __shared__ char smc[];
    const uint32_t sb = smem_u32(smc);
    const int tid = threadIdx.x, lane = tid & 31, warp = tid >> 5;
    const int qt = (int)gridDim.x - 1 - (int)blockIdx.x;   // heavy tiles first
    const int h = blockIdx.y, b = blockIdx.z, kvh = h >> 2;
    const int q0 = qt * AQM;
    const int wm = warp * 16;

    const char* qp = (const char*)(g_q16 + ((size_t)(b * NH + h) * SS + q0) * DH);
    const char* kp = (const char*)(g_k16 + (size_t)(b * KVH + kvh) * SS * DH);
    const char* vp = (const char*)(g_v16 + (size_t)(b * KVH + kvh) * SS * DH);

    // ---- stage Q (128x128 fp16) into smem, ldmatrix to registers --------------
    for (int i = tid; i < 128 * 16; i += 256) {
        int row = i >> 4, ch = (i & 15) << 4;
        cp16(sb + (uint32_t)row * KROW + ch, qp + row * 256 + ch);
    }
    asm volatile("cp.async.commit_group;");
    asm volatile("cp.async.wait_group 0;");
    __syncthreads();

    const int arow = lane & 15, akoff = (lane >> 4) << 3;
    uint32_t qf[8][4];
#pragma unroll
    for (int kc = 0; kc < 8; kc++) {
        uint32_t ra = sb + (uint32_t)(wm + arow) * KROW + ((uint32_t)(kc * 16 + akoff) << 1);
        ldm_x4(qf[kc], ra);
    }
    __syncthreads();   // staging area free for K/V now

    float oacc[16][4];
#pragma unroll
    for (int j = 0; j < 16; j++)
#pragma unroll
        for (int c = 0; c < 4; c++) oacc[j][c] = 0.0f;
    float mrun0 = -INFINITY, mrun1 = -INFINITY;
    float lrun0 = 0.0f, lrun1 = 0.0f;

    const int nblocks = qt + 1;
    const int brow = (lane & 7) + ((lane >> 4) << 3);
    const int bkoff = ((lane >> 3) & 1) << 3;
    const int vrow = lane & 15, vcoff = (lane >> 4) << 3;

    auto issue = [&](int t) {
        const uint32_t base = sb + (uint32_t)(t & 1) * (2 * TB);
        const size_t g0 = (size_t)t * AKN * 256;
        for (int i = tid; i < AKN * 16; i += 256) {
            int row = i >> 4, ch = (i & 15) << 4;
            uint32_t soff = (uint32_t)row * KROW + ch;
            size_t goff = g0 + (size_t)row * 256 + ch;
            cp16(base + soff,      kp + goff);
            cp16(base + TB + soff, vp + goff);
        }
        asm volatile("cp.async.commit_group;");
    };

    issue(0);

    for (int t = 0; t < nblocks; t++) {
        if (t + 1 < nblocks) { issue(t + 1); asm volatile("cp.async.wait_group 1;"); }
        else                 { asm volatile("cp.async.wait_group 0;"); }
        __syncthreads();
        const uint32_t base = sb + (uint32_t)(t & 1) * (2 * TB);

        // ---- S = Q K^T (single-pass fp16, 16x128 per warp) --------------------
        float sacc[16][4];
#pragma unroll
        for (int j = 0; j < 16; j++)
#pragma unroll
            for (int c = 0; c < 4; c++) sacc[j][c] = 0.0f;

#pragma unroll
        for (int kc = 0; kc < 8; kc++) {
            const uint32_t kb = (uint32_t)(kc * 16 + bkoff) << 1;
#pragma unroll
            for (int np = 0; np < 8; np++) {
                uint32_t rb = base + (uint32_t)(np * 16 + brow) * KROW + kb;
                uint32_t bh4[4];
                ldm_x4(bh4, rb);
#pragma unroll
                for (int ia = 0; ia < 2; ia++)
                    mma_f16(sacc[np * 2 + ia], qf[kc], bh4[2 * ia], bh4[2 * ia + 1]);
            }
        }

        // ---- causal mask (warp-uniform skip when fully unmasked) --------------
        const int k0 = t * AKN;
        if (k0 + AKN - 1 > q0 + wm) {
            const int r0 = q0 + wm + (lane >> 2);
#pragma unroll
            for (int j = 0; j < 16; j++) {
                int cb = k0 + j * 8 + ((lane & 3) << 1);
                if (cb     > r0)     sacc[j][0] = -INFINITY;
                if (cb + 1 > r0)     sacc[j][1] = -INFINITY;
                if (cb     > r0 + 8) sacc[j][2] = -INFINITY;
                if (cb + 1 > r0 + 8) sacc[j][3] = -INFINITY;
            }
        }

        // ---- online softmax ---------------------------------------------------
        float mx0 = -INFINITY, mx1 = -INFINITY;
#pragma unroll
        for (int j = 0; j < 16; j++) {
            mx0 = fmaxf(mx0, fmaxf(sacc[j][0], sacc[j][1]));
            mx1 = fmaxf(mx1, fmaxf(sacc[j][2], sacc[j][3]));
        }
        mx0 = fmaxf(mx0, __shfl_xor_sync(0xffffffffu, mx0, 1));
        mx0 = fmaxf(mx0, __shfl_xor_sync(0xffffffffu, mx0, 2));
        mx1 = fmaxf(mx1, __shfl_xor_sync(0xffffffffu, mx1, 1));
        mx1 = fmaxf(mx1, __shfl_xor_sync(0xffffffffu, mx1, 2));
        float mn0 = fmaxf(mrun0, mx0), mn1 = fmaxf(mrun1, mx1);

        float sum0 = 0.0f, sum1 = 0.0f;
#pragma unroll
        for (int j = 0; j < 16; j++) {
            float e0 = __expf(sacc[j][0] - mn0);
            float e1 = __expf(sacc[j][1] - mn0);
            float e2 = __expf(sacc[j][2] - mn1);
            float e3 = __expf(sacc[j][3] - mn1);
            sacc[j][0] = e0; sacc[j][1] = e1; sacc[j][2] = e2; sacc[j][3] = e3;
            sum0 += e0 + e1; sum1 += e2 + e3;
        }
        sum0 += __shfl_xor_sync(0xffffffffu, sum0, 1);
        sum0 += __shfl_xor_sync(0xffffffffu, sum0, 2);
        sum1 += __shfl_xor_sync(0xffffffffu, sum1, 1);
        sum1 += __shfl_xor_sync(0xffffffffu, sum1, 2);

        float c0 = __expf(mrun0 - mn0), c1 = __expf(mrun1 - mn1);
        lrun0 = lrun0 * c0 + sum0;
        lrun1 = lrun1 * c1 + sum1;
        mrun0 = mn0; mrun1 = mn1;
#pragma unroll
        for (int j = 0; j < 16; j++) {
            oacc[j][0] *= c0; oacc[j][1] *= c0;
            oacc[j][2] *= c1; oacc[j][3] *= c1;
        }

        // ---- O += P V (single-pass fp16, k=128 keys in 8 chunks) --------------
#pragma unroll
        for (int kc = 0; kc < 8; kc++) {
            uint32_t pa[4];
            __half2 p0 = __floats2half2_rn(sacc[2*kc][0],   sacc[2*kc][1]);
            __half2 p1 = __floats2half2_rn(sacc[2*kc][2],   sacc[2*kc][3]);
            __half2 p2 = __floats2half2_rn(sacc[2*kc+1][0], sacc[2*kc+1][1]);
            __half2 p3 = __floats2half2_rn(sacc[2*kc+1][2], sacc[2*kc+1][3]);
            pa[0] = *(uint32_t*)&p0; pa[1] = *(uint32_t*)&p1;
            pa[2] = *(uint32_t*)&p2; pa[3] = *(uint32_t*)&p3;
#pragma unroll
            for (int nd = 0; nd < 8; nd++) {
                uint32_t rv = base + TB + (uint32_t)(kc * 16 + vrow) * KROW
                              + ((uint32_t)(nd * 16 + vcoff) << 1);
                uint32_t vh4[4];
                ldm_x4_t(vh4, rv);
#pragma unroll
                for (int ia = 0; ia < 2; ia++)
                    mma_f16(oacc[nd * 2 + ia], pa, vh4[2 * ia], vh4[2 * ia + 1]);
            }
        }
        __syncthreads();
    }

    // ---- epilogue: normalize, write single fp16 for the Wo GEMM ----------------
    const float inv0 = 1.0f / lrun0, inv1 = 1.0f / lrun1;
    const size_t r0 = (size_t)(b * SS + q0 + wm + (lane >> 2)) * (NH * DH)
                      + h * DH + ((lane & 3) << 1);
    const size_t r1 = r0 + (size_t)8 * (NH * DH);
#pragma unroll
    for (int nd = 0; nd < 16; nd++) {
        __half2 h0 = __floats2half2_rn(oacc[nd][0] * inv0, oacc[nd][1] * inv0);
        __half2 h1 = __floats2half2_rn(oacc[nd][2] * inv1, oacc[nd][3] * inv1);
        *(__half2*)(g_att16 + r0 + nd * 8) = h0;
        *(__half2*)(g_att16 + r1 + nd * 8) = h1;
    }
}

// ---------------- launch --------------------------------------------------------
extern "C" void kernel_launch(void* const* d_in, const int* in_sizes, int n_in,
                              void* d_out, int out_size)
{
    const float* x   = (const float*)d_in[0];
    // d_in[1] = mask (causal; handled analytically)
    const int*   pos = (const int*)d_in[2];
    const float* Wq  = (const float*)d_in[3];
    const float* Wk  = (const float*)d_in[4];
    const float* Wv  = (const float*)d_in[5];
    const float* Wo  = (const float*)d_in[6];
    float* out = (float*)d_out;

    float* qkvraw;
    cudaGetSymbolAddress((void**)&qkvraw, g_qkvraw);
    __half *x16, *wqkv, *wo, *att16;
    cudaGetSymbolAddress((void**)&x16,   g_x16);
    cudaGetSymbolAddress((void**)&wqkv,  g_wqkv16);
    cudaGetSymbolAddress((void**)&wo,    g_wo16);
    cudaGetSymbolAddress((void**)&att16, g_att16);

    cudaFuncSetAttribute(attn_kernel,
                         cudaFuncAttributeMaxDynamicSharedMemorySize, AT_SMEM);
    cudaFuncSetAttribute(mm_f16_kernel,
                         cudaFuncAttributeMaxDynamicSharedMemorySize, MM_SMEM);

    // convert x to fp16; transpose+convert all weights in ONE launch
    cvt16_kernel<<<(MROWS * DIM / 4 + 255) / 256, 256>>>(x, x16, MROWS * DIM / 4);
    cvtT16_all_kernel<<<dim3(DIM / 32, DIM / 32, 4), dim3(32, 8)>>>(Wq, Wk, Wv, Wo);

    // fused QKV projection (fp16 single-pass, one launch, N=3072)
    mm_f16_kernel<<<dim3(NQKV / 128, MROWS / 128), 128, MM_SMEM>>>(
        x16, wqkv, qkvraw, NQKV);

    // RoPE -> fp16 attention operands
    rope_kernel<<<dim3(SS, BB), 256>>>(pos);

    // attention on tensor cores (fp16 single-pass, 128-wide K tiles)
    attn_kernel<<<dim3(SS / AQM, NH, BB), 256, AT_SMEM>>>();

    // output projection (fp16 single-pass)
    mm_f16_kernel<<<dim3(DIM / 128, MROWS / 128), 128, MM_SMEM>>>(
        att16, wo, out, DIM);
}

// round 14
// speedup vs baseline: 1.0556x; 1.0073x over previous
#include <cuda_runtime.h>
#include <cuda_bf16.h>
#include <cuda_fp16.h>
#include <math.h>
#include <stdint.h>

// Problem constants
#define BB 2
#define SS 2048
#define DIM 2048
#define NH 16
#define KVH 4
#define DH 128
#define MROWS (BB * SS)   // 4096
#define NQKV 3072         // fused QKV output width (2048 q + 512 k + 512 v)

// ---------------- scratch (device globals; no allocation allowed) -------------
__device__ __half g_qkv16i[MROWS * NQKV];       // fused QKV projection output (fp16)

// attention operands (fp16), layout [b,h,s,d]
__device__ __half g_q16[BB * NH * SS * DH];     // Q (scale folded)
__device__ __half g_k16[BB * KVH * SS * DH];    // K
__device__ __half g_v16[BB * KVH * SS * DH];    // V

// fp16 GEMM operands
__device__ __half g_x16[MROWS * DIM];           // x
__device__ __half g_wqkv16[NQKV * DIM];         // fused W_qkv, transposed [N][K]
__device__ __half g_wo16[DIM * DIM];            // W_o, transposed [N][K]
__device__ __half g_att16[MROWS * (NH*DH)];     // attention output

// ---------------- PTX helpers ---------------------------------------------------
__device__ __forceinline__ uint32_t smem_u32(const void* p) {
    uint32_t a;
    asm("{ .reg .u64 t; cvta.to.shared.u64 t, %1; cvt.u32.u64 %0, t; }"
        : "=r"(a) : "l"(p));
    return a;
}

__device__ __forceinline__ void cp16(uint32_t dst, const void* src) {
    asm volatile("cp.async.cg.shared.global [%0], [%1], 16;\n"
                 :: "r"(dst), "l"(src));
}

__device__ __forceinline__ void ldm_x4(uint32_t r[4], uint32_t addr) {
    asm volatile("ldmatrix.sync.aligned.m8n8.x4.shared.b16 {%0,%1,%2,%3}, [%4];"
                 : "=r"(r[0]), "=r"(r[1]), "=r"(r[2]), "=r"(r[3]) : "r"(addr));
}

__device__ __forceinline__ void ldm_x4_t(uint32_t r[4], uint32_t addr) {
    asm volatile("ldmatrix.sync.aligned.m8n8.x4.trans.shared.b16 {%0,%1,%2,%3}, [%4];"
                 : "=r"(r[0]), "=r"(r[1]), "=r"(r[2]), "=r"(r[3]) : "r"(addr));
}

__device__ __forceinline__ void mma_f16(float c[4], const uint32_t a[4],
                                        uint32_t b0, uint32_t b1) {
    asm volatile(
        "mma.sync.aligned.m16n8k16.row.col.f32.f16.f16.f32 "
        "{%0,%1,%2,%3}, {%4,%5,%6,%7}, {%8,%9}, {%0,%1,%2,%3};"
        : "+f"(c[0]), "+f"(c[1]), "+f"(c[2]), "+f"(c[3])
        : "r"(a[0]), "r"(a[1]), "r"(a[2]), "r"(a[3]), "r"(b0), "r"(b1));
}

// ---------------- fp32 -> fp16 single convert ----------------------------------
__global__ __launch_bounds__(256) void cvt16_kernel(
    const float* __restrict__ in, __half* __restrict__ out, int n4)
{
    int i = blockIdx.x * blockDim.x + threadIdx.x;
    if (i >= n4) return;
    float4 v = ((const float4*)in)[i];
    __half2 a = __floats2half2_rn(v.x, v.y);
    __half2 b = __floats2half2_rn(v.z, v.w);
    ((__half2*)out)[2*i]   = a;
    ((__half2*)out)[2*i+1] = b;
}

// ---------------- all weights: fp32 [K][N] -> fp16 transposed [N][K], one launch -
__global__ __launch_bounds__(256) void cvtT16_all_kernel(
    const float* __restrict__ Wq, const float* __restrict__ Wk,
    const float* __restrict__ Wv, const float* __restrict__ Wo)
{
    const int z = blockIdx.z;
    const float* W;
    __half* T;
    int N;
    if (z == 0)      { W = Wq; T = g_wqkv16;                        N = DIM; }
    else if (z == 1) { W = Wk; T = g_wqkv16 + (size_t)2048 * DIM;   N = KVH * DH; }
    else if (z == 2) { W = Wv; T = g_wqkv16 + (size_t)2560 * DIM;   N = KVH * DH; }
    else             { W = Wo; T = g_wo16;                          N = DIM; }
    if (blockIdx.x * 32 >= N) return;

    __shared__ float t[32][33];
    const int n0 = blockIdx.x * 32, k0 = blockIdx.y * 32;
    const int tx = threadIdx.x, ty = threadIdx.y;   // (32, 8)
    for (int i = ty; i < 32; i += 8)
        t[i][tx] = W[(size_t)(k0 + i) * N + n0 + tx];
    __syncthreads();
    for (int i = ty; i < 32; i += 8)
        T[(size_t)(n0 + i) * DIM + k0 + tx] = __float2half_rn(t[tx][i]);
}

// ---------------- fp16 mma.sync single-pass GEMM --------------------------------
// C[M,N] = A @ B^T.  A:[M][K] fp16, B:[N][K] fp16. OutT = float or __half.
// 4 warps, warp tile 64x64; CTA 128x128, BK=32, double-buffered cp.async.
#define GK 2048
#define ROWB 80
#define TILE_B (128 * ROWB)
#define OFF_A  0
#define OFF_B  (1 * TILE_B)
#define STG (2 * TILE_B)
#define MM_SMEM (2 * STG)   // 40960

template <typename OutT>
__global__ __launch_bounds__(128) void mm_f16_kernel(
    const __half* __restrict__ A, const __half* __restrict__ B,
    OutT* __restrict__ C, int N)
{
    extern __shared__ char smem[];
    const uint32_t sb = smem_u32(smem);
    const int tid = threadIdx.x;
    const int lane = tid & 31, warp = tid >> 5;
    const int m0 = blockIdx.y * 128, n0 = blockIdx.x * 128;
    const int wm0 = (warp >> 1) * 64;
    const int wn0 = (warp & 1) * 64;

    const int arow_l  = lane & 15;
    const int akoff_l = (lane >> 4) << 3;
    const int brow_l  = (lane & 7) + ((lane >> 4) << 3);
    const int bkoff_l = ((lane >> 3) & 1) << 3;

    float acc[4][8][4];
#pragma unroll
    for (int im = 0; im < 4; im++)
#pragma unroll
        for (int j = 0; j < 8; j++)
#pragma unroll
            for (int c = 0; c < 4; c++) acc[im][j][c] = 0.0f;

    const int NT = GK / 32;

    auto issue = [&](int t) {
        const int k0 = t * 32;
        const uint32_t sbase = sb + (t & 1) * STG;
#pragma unroll
        for (int i = 0; i < 4; i++) {
            const int c = tid + (i << 7);
            const int row = c >> 2;
            const int off = (c & 3) << 3;
            const uint32_t soff = (uint32_t)row * ROWB + ((uint32_t)off << 1);
            cp16(sbase + OFF_A + soff, A + (size_t)(m0 + row) * GK + k0 + off);
            cp16(sbase + OFF_B + soff, B + (size_t)(n0 + row) * GK + k0 + off);
        }
        asm volatile("cp.async.commit_group;");
    };

    issue(0);

    for (int t = 0; t < NT; t++) {
        if (t + 1 < NT) issue(t + 1);
        if (t + 1 < NT) { asm volatile("cp.async.wait_group 1;"); }
        else            { asm volatile("cp.async.wait_group 0;"); }
        __syncthreads();

        const uint32_t sbase = sb + (t & 1) * STG;
#pragma unroll
        for (int ks = 0; ks < 2; ks++) {
            uint32_t ah[4][4];
            const uint32_t kba = (uint32_t)(ks * 16 + akoff_l) << 1;
#pragma unroll
            for (int im = 0; im < 4; im++) {
                uint32_t ra = sbase + (uint32_t)(wm0 + im * 16 + arow_l) * ROWB + kba;
                ldm_x4(ah[im], ra + OFF_A);
            }
            const uint32_t kbb = (uint32_t)(ks * 16 + bkoff_l) << 1;
#pragma unroll
            for (int np = 0; np < 4; np++) {
                uint32_t rb = sbase + (uint32_t)(wn0 + np * 16 + brow_l) * ROWB + kbb;
                uint32_t bh[4];
                ldm_x4(bh, rb + OFF_B);
#pragma unroll
                for (int im = 0; im < 4; im++) {
#pragma unroll
                    for (int ia = 0; ia < 2; ia++)
                        mma_f16(acc[im][np * 2 + ia], ah[im],
                                bh[2 * ia], bh[2 * ia + 1]);
                }
            }
        }
        __syncthreads();
    }

#pragma unroll
    for (int im = 0; im < 4; im++) {
        const int rbase = m0 + wm0 + im * 16 + (lane >> 2);
#pragma unroll
        for (int j = 0; j < 8; j++) {
            const int col = n0 + wn0 + j * 8 + (lane & 3) * 2;
            if constexpr (sizeof(OutT) == 4) {
                float2 v0 = make_float2(acc[im][j][0], acc[im][j][1]);
                float2 v1 = make_float2(acc[im][j][2], acc[im][j][3]);
                *(float2*)((float*)C + (size_t)rbase * N + col)       = v0;
                *(float2*)((float*)C + (size_t)(rbase + 8) * N + col) = v1;
            } else {
                __half2 v0 = __floats2half2_rn(acc[im][j][0], acc[im][j][1]);
                __half2 v1 = __floats2half2_rn(acc[im][j][2], acc[im][j][3]);
                *(__half2*)((__half*)C + (size_t)rbase * N + col)       = v0;
                *(__half2*)((__half*)C + (size_t)(rbase + 8) * N + col) = v1;
            }
        }
    }
}

// ---------------- RoPE (fp16 in) -> fp16 attention operands [b,h,s,d] -----------
__global__ __launch_bounds__(256) void rope_kernel(const int* __restrict__ pos_ids)
{
    const int s = blockIdx.x;
    const int b = blockIdx.y;
    const int t = threadIdx.x;

    __shared__ float cs[64], sn[64];
    if (t < 64) {
        double invf = exp(-((double)(2 * t) / (double)DH) * log(10000.0));
        double ang = (double)pos_ids[s] * invf;
        cs[t] = (float)cos(ang);
        sn[t] = (float)sin(ang);
    }
    __syncthreads();

    const float qk_scale = 0.08838834764831845f;   // 1/sqrt(128), folded into Q
    const __half* row = g_qkv16i + (size_t)(b * SS + s) * NQKV;

    // Q: rotate + scale
    for (int idx = t; idx < NH * 64; idx += 256) {
        int h = idx >> 6, i = idx & 63;
        float x1 = __half2float(row[h * DH + i]);
        float x2 = __half2float(row[h * DH + 64 + i]);
        size_t dst = ((size_t)(b * NH + h) * SS + s) * DH;
        g_q16[dst + i]      = __float2half_rn((x1 * cs[i] - x2 * sn[i]) * qk_scale);
        g_q16[dst + 64 + i] = __float2half_rn((x2 * cs[i] + x1 * sn[i]) * qk_scale);
    }

    // K: rotate
    const __half* krow = row + 2048;
    for (int idx = t; idx < KVH * 64; idx += 256) {
        int h = idx >> 6, i = idx & 63;
        float x1 = __half2float(krow[h * DH + i]);
        float x2 = __half2float(krow[h * DH + 64 + i]);
        size_t dst = ((size_t)(b * KVH + h) * SS + s) * DH;
        g_k16[dst + i]      = __float2half_rn(x1 * cs[i] - x2 * sn[i]);
        g_k16[dst + 64 + i] = __float2half_rn(x2 * cs[i] + x1 * sn[i]);
    }

    // V: relayout copy (fp16 -> fp16, vectorized)
    const __half* vrow = row + 2560;
    for (int idx = t; idx < KVH * DH / 2; idx += 256) {
        int h = idx >> 6, d2 = idx & 63;
        __half2 v = *(const __half2*)(vrow + h * DH + d2 * 2);
        *(__half2*)(g_v16 + ((size_t)(b * KVH + h) * SS + s) * DH + d2 * 2) = v;
    }
}

// ---------------- flash attention (fp16 mma.sync, causal, GQA) ------------------
// CTA: 128 q rows x 128-key blocks. 8 warps x 16 q rows.
#define AQM 128
#define AKN 128
#define KROW 272                  // smem row stride bytes (256 data + 16 pad)
#define TB (AKN * KROW)           // 34816
#define AT_SMEM (4 * TB)          // 139264: 2 stages x (K, V)

__global__ __launch_bounds__(256) void attn_kernel()
{
    extern __shared__ char smc[];
    const uint32_t sb = smem_u32(smc);
    const int tid = threadIdx.x, lane = tid & 31, warp = tid >> 5;
    const int qt = (int)gridDim.x - 1 - (int)blockIdx.x;   // heavy tiles first
    const int h = blockIdx.y, b = blockIdx.z, kvh = h >> 2;
    const int q0 = qt * AQM;
    const int wm = warp * 16;

    const char* qp = (const char*)(g_q16 + ((size_t)(b * NH + h) * SS + q0) * DH);
    const char* kp = (const char*)(g_k16 + (size_t)(b * KVH + kvh) * SS * DH);
    const char* vp = (const char*)(g_v16 + (size_t)(b * KVH + kvh) * SS * DH);

    // ---- stage Q (128x128 fp16) into smem, ldmatrix to registers --------------
    for (int i = tid; i < 128 * 16; i += 256) {
        int row = i >> 4, ch = (i & 15) << 4;
        cp16(sb + (uint32_t)row * KROW + ch, qp + row * 256 + ch);
    }
    asm volatile("cp.async.commit_group;");
    asm volatile("cp.async.wait_group 0;");
    __syncthreads();

    const int arow = lane & 15, akoff = (lane >> 4) << 3;
    uint32_t qf[8][4];
#pragma unroll
    for (int kc = 0; kc < 8; kc++) {
        uint32_t ra = sb + (uint32_t)(wm + arow) * KROW + ((uint32_t)(kc * 16 + akoff) << 1);
        ldm_x4(qf[kc], ra);
    }
    __syncthreads();   // staging area free for K/V now

    float oacc[16][4];
#pragma unroll
    for (int j = 0; j < 16; j++)
#pragma unroll
        for (int c = 0; c < 4; c++) oacc[j][c] = 0.0f;
    float mrun0 = -INFINITY, mrun1 = -INFINITY;
    float lrun0 = 0.0f, lrun1 = 0.0f;

    const int nblocks = qt + 1;
    const int brow = (lane & 7) + ((lane >> 4) << 3);
    const int bkoff = ((lane >> 3) & 1) << 3;
    const int vrow = lane & 15, vcoff = (lane >> 4) << 3;

    auto issue = [&](int t) {
        const uint32_t base = sb + (uint32_t)(t & 1) * (2 * TB);
        const size_t g0 = (size_t)t * AKN * 256;
        for (int i = tid; i < AKN * 16; i += 256) {
            int row = i >> 4, ch = (i & 15) << 4;
            uint32_t soff = (uint32_t)row * KROW + ch;
            size_t goff = g0 + (size_t)row * 256 + ch;
            cp16(base + soff,      kp + goff);
            cp16(base + TB + soff, vp + goff);
        }
        asm volatile("cp.async.commit_group;");
    };

    issue(0);

    for (int t = 0; t < nblocks; t++) {
        if (t + 1 < nblocks) { issue(t + 1); asm volatile("cp.async.wait_group 1;"); }
        else                 { asm volatile("cp.async.wait_group 0;"); }
        __syncthreads();
        const uint32_t base = sb + (uint32_t)(t & 1) * (2 * TB);

        // ---- S = Q K^T (single-pass fp16, 16x128 per warp) --------------------
        float sacc[16][4];
#pragma unroll
        for (int j = 0; j < 16; j++)
#pragma unroll
            for (int c = 0; c < 4; c++) sacc[j][c] = 0.0f;

#pragma unroll
        for (int kc = 0; kc < 8; kc++) {
            const uint32_t kb = (uint32_t)(kc * 16 + bkoff) << 1;
#pragma unroll
            for (int np = 0; np < 8; np++) {
                uint32_t rb = base + (uint32_t)(np * 16 + brow) * KROW + kb;
                uint32_t bh4[4];
                ldm_x4(bh4, rb);
#pragma unroll
                for (int ia = 0; ia < 2; ia++)
                    mma_f16(sacc[np * 2 + ia], qf[kc], bh4[2 * ia], bh4[2 * ia + 1]);
            }
        }

        // ---- causal mask (warp-uniform skip when fully unmasked) --------------
        const int k0 = t * AKN;
        if (k0 + AKN - 1 > q0 + wm) {
            const int r0 = q0 + wm + (lane >> 2);
#pragma unroll
            for (int j = 0; j < 16; j++) {
                int cb = k0 + j * 8 + ((lane & 3) << 1);
                if (cb     > r0)     sacc[j][0] = -INFINITY;
                if (cb + 1 > r0)     sacc[j][1] = -INFINITY;
                if (cb     > r0 + 8) sacc[j][2] = -INFINITY;
                if (cb + 1 > r0 + 8) sacc[j][3] = -INFINITY;
            }
        }

        // ---- online softmax ---------------------------------------------------
        float mx0 = -INFINITY, mx1 = -INFINITY;
#pragma unroll
        for (int j = 0; j < 16; j++) {
            mx0 = fmaxf(mx0, fmaxf(sacc[j][0], sacc[j][1]));
            mx1 = fmaxf(mx1, fmaxf(sacc[j][2], sacc[j][3]));
        }
        mx0 = fmaxf(mx0, __shfl_xor_sync(0xffffffffu, mx0, 1));
        mx0 = fmaxf(mx0, __shfl_xor_sync(0xffffffffu, mx0, 2));
        mx1 = fmaxf(mx1, __shfl_xor_sync(0xffffffffu, mx1, 1));
        mx1 = fmaxf(mx1, __shfl_xor_sync(0xffffffffu, mx1, 2));
        float mn0 = fmaxf(mrun0, mx0), mn1 = fmaxf(mrun1, mx1);

        float sum0 = 0.0f, sum1 = 0.0f;
#pragma unroll
        for (int j = 0; j < 16; j++) {
            float e0 = __expf(sacc[j][0] - mn0);
            float e1 = __expf(sacc[j][1] - mn0);
            float e2 = __expf(sacc[j][2] - mn1);
            float e3 = __expf(sacc[j][3] - mn1);
            sacc[j][0] = e0; sacc[j][1] = e1; sacc[j][2] = e2; sacc[j][3] = e3;
            sum0 += e0 + e1; sum1 += e2 + e3;
        }
        sum0 += __shfl_xor_sync(0xffffffffu, sum0, 1);
        sum0 += __shfl_xor_sync(0xffffffffu, sum0, 2);
        sum1 += __shfl_xor_sync(0xffffffffu, sum1, 1);
        sum1 += __shfl_xor_sync(0xffffffffu, sum1, 2);

        float c0 = __expf(mrun0 - mn0), c1 = __expf(mrun1 - mn1);
        lrun0 = lrun0 * c0 + sum0;
        lrun1 = lrun1 * c1 + sum1;
        mrun0 = mn0; mrun1 = mn1;
#pragma unroll
        for (int j = 0; j < 16; j++) {
            oacc[j][0] *= c0; oacc[j][1] *= c0;
            oacc[j][2] *= c1; oacc[j][3] *= c1;
        }

        // ---- O += P V (single-pass fp16, k=128 keys in 8 chunks) --------------
#pragma unroll
        for (int kc = 0; kc < 8; kc++) {
            uint32_t pa[4];
            __half2 p0 = __floats2half2_rn(sacc[2*kc][0],   sacc[2*kc][1]);
            __half2 p1 = __floats2half2_rn(sacc[2*kc][2],   sacc[2*kc][3]);
            __half2 p2 = __floats2half2_rn(sacc[2*kc+1][0], sacc[2*kc+1][1]);
            __half2 p3 = __floats2half2_rn(sacc[2*kc+1][2], sacc[2*kc+1][3]);
            pa[0] = *(uint32_t*)&p0; pa[1] = *(uint32_t*)&p1;
            pa[2] = *(uint32_t*)&p2; pa[3] = *(uint32_t*)&p3;
#pragma unroll
            for (int nd = 0; nd < 8; nd++) {
                uint32_t rv = base + TB + (uint32_t)(kc * 16 + vrow) * KROW
                              + ((uint32_t)(nd * 16 + vcoff) << 1);
                uint32_t vh4[4];
                ldm_x4_t(vh4, rv);
#pragma unroll
                for (int ia = 0; ia < 2; ia++)
                    mma_f16(oacc[nd * 2 + ia], pa, vh4[2 * ia], vh4[2 * ia + 1]);
            }
        }
        __syncthreads();
    }

    // ---- epilogue: normalize, write single fp16 for the Wo GEMM ----------------
    const float inv0 = 1.0f / lrun0, inv1 = 1.0f / lrun1;
    const size_t r0 = (size_t)(b * SS + q0 + wm + (lane >> 2)) * (NH * DH)
                      + h * DH + ((lane & 3) << 1);
    const size_t r1 = r0 + (size_t)8 * (NH * DH);
#pragma unroll
    for (int nd = 0; nd < 16; nd++) {
        __half2 h0 = __floats2half2_rn(oacc[nd][0] * inv0, oacc[nd][1] * inv0);
        __half2 h1 = __floats2half2_rn(oacc[nd][2] * inv1, oacc[nd][3] * inv1);
        *(__half2*)(g_att16 + r0 + nd * 8) = h0;
        *(__half2*)(g_att16 + r1 + nd * 8) = h1;
    }
}

// ---------------- launch --------------------------------------------------------
extern "C" void kernel_launch(void* const* d_in, const int* in_sizes, int n_in,
                              void* d_out, int out_size)
{
    const float* x   = (const float*)d_in[0];
    // d_in[1] = mask (causal; handled analytically)
    const int*   pos = (const int*)d_in[2];
    const float* Wq  = (const float*)d_in[3];
    const float* Wk  = (const float*)d_in[4];
    const float* Wv  = (const float*)d_in[5];
    const float* Wo  = (const float*)d_in[6];
    float* out = (float*)d_out;

    __half *qkv16i, *x16, *wqkv, *wo, *att16;
    cudaGetSymbolAddress((void**)&qkv16i, g_qkv16i);
    cudaGetSymbolAddress((void**)&x16,    g_x16);
    cudaGetSymbolAddress((void**)&wqkv,   g_wqkv16);
    cudaGetSymbolAddress((void**)&wo,     g_wo16);
    cudaGetSymbolAddress((void**)&att16,  g_att16);

    cudaFuncSetAttribute(attn_kernel,
                         cudaFuncAttributeMaxDynamicSharedMemorySize, AT_SMEM);
    cudaFuncSetAttribute(mm_f16_kernel<float>,
                         cudaFuncAttributeMaxDynamicSharedMemorySize, MM_SMEM);
    cudaFuncSetAttribute(mm_f16_kernel<__half>,
                         cudaFuncAttributeMaxDynamicSharedMemorySize, MM_SMEM);

    // convert x to fp16; transpose+convert all weights in ONE launch
    cvt16_kernel<<<(MROWS * DIM / 4 + 255) / 256, 256>>>(x, x16, MROWS * DIM / 4);
    cvtT16_all_kernel<<<dim3(DIM / 32, DIM / 32, 4), dim3(32, 8)>>>(Wq, Wk, Wv, Wo);

    // fused QKV projection (fp16 single-pass, fp16 output)
    mm_f16_kernel<__half><<<dim3(NQKV / 128, MROWS / 128), 128, MM_SMEM>>>(
        x16, wqkv, qkv16i, NQKV);

    // RoPE -> fp16 attention operands
    rope_kernel<<<dim3(SS, BB), 256>>>(pos);

    // attention on tensor cores (fp16 single-pass, 128-wide K tiles)
    attn_kernel<<<dim3(SS / AQM, NH, BB), 256, AT_SMEM>>>();

    // output projection (fp16 single-pass, fp32 output)
    mm_f16_kernel<float><<<dim3(DIM / 128, MROWS / 128), 128, MM_SMEM>>>(
        att16, wo, out, DIM);
}

// round 15
// speedup vs baseline: 1.0595x; 1.0037x over previous
#include <cuda_runtime.h>
#include <cuda_bf16.h>
#include <cuda_fp16.h>
#include <math.h>
#include <stdint.h>

// Problem constants
#define BB 2
#define SS 2048
#define DIM 2048
#define NH 16
#define KVH 4
#define DH 128
#define MROWS (BB * SS)   // 4096
#define NQKV 3072         // fused QKV output width (2048 q + 512 k + 512 v)

// ---------------- scratch (device globals; no allocation allowed) -------------
__device__ __half g_qkv16i[MROWS * NQKV];       // fused QKV projection output (fp16)

// attention operands (fp16), layout [b,h,s,d]
__device__ __half g_q16[BB * NH * SS * DH];     // Q (scale folded)
__device__ __half g_k16[BB * KVH * SS * DH];    // K
__device__ __half g_v16[BB * KVH * SS * DH];    // V

// fp16 GEMM operands
__device__ __half g_x16[MROWS * DIM];           // x
__device__ __half g_wqkv16[NQKV * DIM];         // fused W_qkv, transposed [N][K]
__device__ __half g_wo16[DIM * DIM];            // W_o, transposed [N][K]
__device__ __half g_att16[MROWS * (NH*DH)];     // attention output

// ---------------- PTX helpers ---------------------------------------------------
__device__ __forceinline__ uint32_t smem_u32(const void* p) {
    uint32_t a;
    asm("{ .reg .u64 t; cvta.to.shared.u64 t, %1; cvt.u32.u64 %0, t; }"
        : "=r"(a) : "l"(p));
    return a;
}

__device__ __forceinline__ void cp16(uint32_t dst, const void* src) {
    asm volatile("cp.async.cg.shared.global [%0], [%1], 16;\n"
                 :: "r"(dst), "l"(src));
}

__device__ __forceinline__ void ldm_x4(uint32_t r[4], uint32_t addr) {
    asm volatile("ldmatrix.sync.aligned.m8n8.x4.shared.b16 {%0,%1,%2,%3}, [%4];"
                 : "=r"(r[0]), "=r"(r[1]), "=r"(r[2]), "=r"(r[3]) : "r"(addr));
}

__device__ __forceinline__ void ldm_x4_t(uint32_t r[4], uint32_t addr) {
    asm volatile("ldmatrix.sync.aligned.m8n8.x4.trans.shared.b16 {%0,%1,%2,%3}, [%4];"
                 : "=r"(r[0]), "=r"(r[1]), "=r"(r[2]), "=r"(r[3]) : "r"(addr));
}

__device__ __forceinline__ void mma_f16(float c[4], const uint32_t a[4],
                                        uint32_t b0, uint32_t b1) {
    asm volatile(
        "mma.sync.aligned.m16n8k16.row.col.f32.f16.f16.f32 "
        "{%0,%1,%2,%3}, {%4,%5,%6,%7}, {%8,%9}, {%0,%1,%2,%3};"
        : "+f"(c[0]), "+f"(c[1]), "+f"(c[2]), "+f"(c[3])
        : "r"(a[0]), "r"(a[1]), "r"(a[2]), "r"(a[3]), "r"(b0), "r"(b1));
}

// ---------------- fp32 -> fp16 single convert ----------------------------------
__global__ __launch_bounds__(256) void cvt16_kernel(
    const float* __restrict__ in, __half* __restrict__ out, int n4)
{
    int i = blockIdx.x * blockDim.x + threadIdx.x;
    if (i >= n4) return;
    float4 v = ((const float4*)in)[i];
    __half2 a = __floats2half2_rn(v.x, v.y);
    __half2 b = __floats2half2_rn(v.z, v.w);
    ((__half2*)out)[2*i]   = a;
    ((__half2*)out)[2*i+1] = b;
}

// ---------------- all weights: fp32 [K][N] -> fp16 transposed [N][K], one launch -
__global__ __launch_bounds__(256) void cvtT16_all_kernel(
    const float* __restrict__ Wq, const float* __restrict__ Wk,
    const float* __restrict__ Wv, const float* __restrict__ Wo)
{
    const int z = blockIdx.z;
    const float* W;
    __half* T;
    int N;
    if (z == 0)      { W = Wq; T = g_wqkv16;                        N = DIM; }
    else if (z == 1) { W = Wk; T = g_wqkv16 + (size_t)2048 * DIM;   N = KVH * DH; }
    else if (z == 2) { W = Wv; T = g_wqkv16 + (size_t)2560 * DIM;   N = KVH * DH; }
    else             { W = Wo; T = g_wo16;                          N = DIM; }
    if (blockIdx.x * 32 >= N) return;

    __shared__ float t[32][33];
    const int n0 = blockIdx.x * 32, k0 = blockIdx.y * 32;
    const int tx = threadIdx.x, ty = threadIdx.y;   // (32, 8)
    for (int i = ty; i < 32; i += 8)
        t[i][tx] = W[(size_t)(k0 + i) * N + n0 + tx];
    __syncthreads();
    for (int i = ty; i < 32; i += 8)
        T[(size_t)(n0 + i) * DIM + k0 + tx] = __float2half_rn(t[tx][i]);
}

// ---------------- fp16 mma.sync single-pass GEMM --------------------------------
// C[M,N] = A @ B^T.  A:[M][K] fp16, B:[N][K] fp16. OutT = float or __half.
// 4 warps, warp tile 64x64; CTA 128x128, BK=32, double-buffered cp.async.
#define GK 2048
#define ROWB 80
#define TILE_B (128 * ROWB)
#define OFF_A  0
#define OFF_B  (1 * TILE_B)
#define STG (2 * TILE_B)
#define MM_SMEM (2 * STG)   // 40960

template <typename OutT>
__global__ __launch_bounds__(128) void mm_f16_kernel(
    const __half* __restrict__ A, const __half* __restrict__ B,
    OutT* __restrict__ C, int N)
{
    extern __shared__ char smem[];
    const uint32_t sb = smem_u32(smem);
    const int tid = threadIdx.x;
    const int lane = tid & 31, warp = tid >> 5;
    const int m0 = blockIdx.y * 128, n0 = blockIdx.x * 128;
    const int wm0 = (warp >> 1) * 64;
    const int wn0 = (warp & 1) * 64;

    const int arow_l  = lane & 15;
    const int akoff_l = (lane >> 4) << 3;
    const int brow_l  = (lane & 7) + ((lane >> 4) << 3);
    const int bkoff_l = ((lane >> 3) & 1) << 3;

    float acc[4][8][4];
#pragma unroll
    for (int im = 0; im < 4; im++)
#pragma unroll
        for (int j = 0; j < 8; j++)
#pragma unroll
            for (int c = 0; c < 4; c++) acc[im][j][c] = 0.0f;

    const int NT = GK / 32;

    auto issue = [&](int t) {
        const int k0 = t * 32;
        const uint32_t sbase = sb + (t & 1) * STG;
#pragma unroll
        for (int i = 0; i < 4; i++) {
            const int c = tid + (i << 7);
            const int row = c >> 2;
            const int off = (c & 3) << 3;
            const uint32_t soff = (uint32_t)row * ROWB + ((uint32_t)off << 1);
            cp16(sbase + OFF_A + soff, A + (size_t)(m0 + row) * GK + k0 + off);
            cp16(sbase + OFF_B + soff, B + (size_t)(n0 + row) * GK + k0 + off);
        }
        asm volatile("cp.async.commit_group;");
    };

    issue(0);

    for (int t = 0; t < NT; t++) {
        if (t + 1 < NT) issue(t + 1);
        if (t + 1 < NT) { asm volatile("cp.async.wait_group 1;"); }
        else            { asm volatile("cp.async.wait_group 0;"); }
        __syncthreads();

        const uint32_t sbase = sb + (t & 1) * STG;
#pragma unroll
        for (int ks = 0; ks < 2; ks++) {
            uint32_t ah[4][4];
            const uint32_t kba = (uint32_t)(ks * 16 + akoff_l) << 1;
#pragma unroll
            for (int im = 0; im < 4; im++) {
                uint32_t ra = sbase + (uint32_t)(wm0 + im * 16 + arow_l) * ROWB + kba;
                ldm_x4(ah[im], ra + OFF_A);
            }
            const uint32_t kbb = (uint32_t)(ks * 16 + bkoff_l) << 1;
#pragma unroll
            for (int np = 0; np < 4; np++) {
                uint32_t rb = sbase + (uint32_t)(wn0 + np * 16 + brow_l) * ROWB + kbb;
                uint32_t bh[4];
                ldm_x4(bh, rb + OFF_B);
#pragma unroll
                for (int im = 0; im < 4; im++) {
#pragma unroll
                    for (int ia = 0; ia < 2; ia++)
                        mma_f16(acc[im][np * 2 + ia], ah[im],
                                bh[2 * ia], bh[2 * ia + 1]);
                }
            }
        }
        __syncthreads();
    }

#pragma unroll
    for (int im = 0; im < 4; im++) {
        const int rbase = m0 + wm0 + im * 16 + (lane >> 2);
#pragma unroll
        for (int j = 0; j < 8; j++) {
            const int col = n0 + wn0 + j * 8 + (lane & 3) * 2;
            if constexpr (sizeof(OutT) == 4) {
                float2 v0 = make_float2(acc[im][j][0], acc[im][j][1]);
                float2 v1 = make_float2(acc[im][j][2], acc[im][j][3]);
                *(float2*)((float*)C + (size_t)rbase * N + col)       = v0;
                *(float2*)((float*)C + (size_t)(rbase + 8) * N + col) = v1;
            } else {
                __half2 v0 = __floats2half2_rn(acc[im][j][0], acc[im][j][1]);
                __half2 v1 = __floats2half2_rn(acc[im][j][2], acc[im][j][3]);
                *(__half2*)((__half*)C + (size_t)rbase * N + col)       = v0;
                *(__half2*)((__half*)C + (size_t)(rbase + 8) * N + col) = v1;
            }
        }
    }
}

// ---------------- RoPE (fp16 in) -> fp16 attention operands [b,h,s,d] -----------
__global__ __launch_bounds__(256) void rope_kernel(const int* __restrict__ pos_ids)
{
    const int s = blockIdx.x;
    const int b = blockIdx.y;
    const int t = threadIdx.x;

    __shared__ float cs[64], sn[64];
    if (t < 64) {
        double invf = exp(-((double)(2 * t) / (double)DH) * log(10000.0));
        double ang = (double)pos_ids[s] * invf;
        cs[t] = (float)cos(ang);
        sn[t] = (float)sin(ang);
    }
    __syncthreads();

    const float qk_scale = 0.08838834764831845f;   // 1/sqrt(128), folded into Q
    const __half* row = g_qkv16i + (size_t)(b * SS + s) * NQKV;

    // Q: rotate + scale
    for (int idx = t; idx < NH * 64; idx += 256) {
        int h = idx >> 6, i = idx & 63;
        float x1 = __half2float(row[h * DH + i]);
        float x2 = __half2float(row[h * DH + 64 + i]);
        size_t dst = ((size_t)(b * NH + h) * SS + s) * DH;
        g_q16[dst + i]      = __float2half_rn((x1 * cs[i] - x2 * sn[i]) * qk_scale);
        g_q16[dst + 64 + i] = __float2half_rn((x2 * cs[i] + x1 * sn[i]) * qk_scale);
    }

    // K: rotate
    const __half* krow = row + 2048;
    for (int idx = t; idx < KVH * 64; idx += 256) {
        int h = idx >> 6, i = idx & 63;
        float x1 = __half2float(krow[h * DH + i]);
        float x2 = __half2float(krow[h * DH + 64 + i]);
        size_t dst = ((size_t)(b * KVH + h) * SS + s) * DH;
        g_k16[dst + i]      = __float2half_rn(x1 * cs[i] - x2 * sn[i]);
        g_k16[dst + 64 + i] = __float2half_rn(x2 * cs[i] + x1 * sn[i]);
    }

    // V: relayout copy (fp16 -> fp16, vectorized)
    const __half* vrow = row + 2560;
    for (int idx = t; idx < KVH * DH / 2; idx += 256) {
        int h = idx >> 6, d2 = idx & 63;
        __half2 v = *(const __half2*)(vrow + h * DH + d2 * 2);
        *(__half2*)(g_v16 + ((size_t)(b * KVH + h) * SS + s) * DH + d2 * 2) = v;
    }
}

// ---------------- flash attention (fp16 mma.sync, causal, GQA) ------------------
// CTA: 64 q rows x 64-key blocks, 4 warps x 16 q rows, 128 threads.
// ~19K regs + 69.6KB smem per CTA -> 3 CTAs/SM co-resident, softmax phases of
// one CTA overlap MMA phases of the others.
#define AQM 64
#define AKN 64
#define KROW 272                  // smem row stride bytes (256 data + 16 pad)
#define TB (AKN * KROW)           // 17408
#define AT_SMEM (4 * TB)          // 69632: 2 stages x (K, V)

__global__ __launch_bounds__(128) void attn_kernel()
{
    extern __shared__ char smc[];
    const uint32_t sb = smem_u32(smc);
    const int tid = threadIdx.x, lane = tid & 31, warp = tid >> 5;
    const int qt = (int)gridDim.x - 1 - (int)blockIdx.x;   // heavy tiles first
    const int h = blockIdx.y, b = blockIdx.z, kvh = h >> 2;
    const int q0 = qt * AQM;
    const int wm = warp * 16;

    const char* qp = (const char*)(g_q16 + ((size_t)(b * NH + h) * SS + q0) * DH);
    const char* kp = (const char*)(g_k16 + (size_t)(b * KVH + kvh) * SS * DH);
    const char* vp = (const char*)(g_v16 + (size_t)(b * KVH + kvh) * SS * DH);

    // ---- stage Q (64x128 fp16) into smem, ldmatrix to registers ---------------
    for (int i = tid; i < AQM * 16; i += 128) {
        int row = i >> 4, ch = (i & 15) << 4;
        cp16(sb + (uint32_t)row * KROW + ch, qp + row * 256 + ch);
    }
    asm volatile("cp.async.commit_group;");
    asm volatile("cp.async.wait_group 0;");
    __syncthreads();

    const int arow = lane & 15, akoff = (lane >> 4) << 3;
    uint32_t qf[8][4];
#pragma unroll
    for (int kc = 0; kc < 8; kc++) {
        uint32_t ra = sb + (uint32_t)(wm + arow) * KROW + ((uint32_t)(kc * 16 + akoff) << 1);
        ldm_x4(qf[kc], ra);
    }
    __syncthreads();   // staging area free for K/V now

    float oacc[16][4];
#pragma unroll
    for (int j = 0; j < 16; j++)
#pragma unroll
        for (int c = 0; c < 4; c++) oacc[j][c] = 0.0f;
    float mrun0 = -INFINITY, mrun1 = -INFINITY;
    float lrun0 = 0.0f, lrun1 = 0.0f;

    const int nblocks = qt + 1;     // 64-key blocks up to and including diagonal
    const int brow = (lane & 7) + ((lane >> 4) << 3);
    const int bkoff = ((lane >> 3) & 1) << 3;
    const int vrow = lane & 15, vcoff = (lane >> 4) << 3;

    auto issue = [&](int t) {
        const uint32_t base = sb + (uint32_t)(t & 1) * (2 * TB);
        const size_t g0 = (size_t)t * AKN * 256;
        for (int i = tid; i < AKN * 16; i += 128) {
            int row = i >> 4, ch = (i & 15) << 4;
            uint32_t soff = (uint32_t)row * KROW + ch;
            size_t goff = g0 + (size_t)row * 256 + ch;
            cp16(base + soff,      kp + goff);
            cp16(base + TB + soff, vp + goff);
        }
        asm volatile("cp.async.commit_group;");
    };

    issue(0);

    for (int t = 0; t < nblocks; t++) {
        if (t + 1 < nblocks) { issue(t + 1); asm volatile("cp.async.wait_group 1;"); }
        else                 { asm volatile("cp.async.wait_group 0;"); }
        __syncthreads();
        const uint32_t base = sb + (uint32_t)(t & 1) * (2 * TB);

        // ---- S = Q K^T (single-pass fp16, 16x64 per warp) ---------------------
        float sacc[8][4];
#pragma unroll
        for (int j = 0; j < 8; j++)
#pragma unroll
            for (int c = 0; c < 4; c++) sacc[j][c] = 0.0f;

#pragma unroll
        for (int kc = 0; kc < 8; kc++) {
            const uint32_t kb = (uint32_t)(kc * 16 + bkoff) << 1;
#pragma unroll
            for (int np = 0; np < 4; np++) {
                uint32_t rb = base + (uint32_t)(np * 16 + brow) * KROW + kb;
                uint32_t bh4[4];
                ldm_x4(bh4, rb);
#pragma unroll
                for (int ia = 0; ia < 2; ia++)
                    mma_f16(sacc[np * 2 + ia], qf[kc], bh4[2 * ia], bh4[2 * ia + 1]);
            }
        }

        // ---- causal mask (warp-uniform skip when fully unmasked) --------------
        const int k0 = t * AKN;
        if (k0 + AKN - 1 > q0 + wm) {
            const int r0 = q0 + wm + (lane >> 2);
#pragma unroll
            for (int j = 0; j < 8; j++) {
                int cb = k0 + j * 8 + ((lane & 3) << 1);
                if (cb     > r0)     sacc[j][0] = -INFINITY;
                if (cb + 1 > r0)     sacc[j][1] = -INFINITY;
                if (cb     > r0 + 8) sacc[j][2] = -INFINITY;
                if (cb + 1 > r0 + 8) sacc[j][3] = -INFINITY;
            }
        }

        // ---- online softmax ---------------------------------------------------
        float mx0 = -INFINITY, mx1 = -INFINITY;
#pragma unroll
        for (int j = 0; j < 8; j++) {
            mx0 = fmaxf(mx0, fmaxf(sacc[j][0], sacc[j][1]));
            mx1 = fmaxf(mx1, fmaxf(sacc[j][2], sacc[j][3]));
        }
        mx0 = fmaxf(mx0, __shfl_xor_sync(0xffffffffu, mx0, 1));
        mx0 = fmaxf(mx0, __shfl_xor_sync(0xffffffffu, mx0, 2));
        mx1 = fmaxf(mx1, __shfl_xor_sync(0xffffffffu, mx1, 1));
        mx1 = fmaxf(mx1, __shfl_xor_sync(0xffffffffu, mx1, 2));
        float mn0 = fmaxf(mrun0, mx0), mn1 = fmaxf(mrun1, mx1);

        float sum0 = 0.0f, sum1 = 0.0f;
#pragma unroll
        for (int j = 0; j < 8; j++) {
            float e0 = __expf(sacc[j][0] - mn0);
            float e1 = __expf(sacc[j][1] - mn0);
            float e2 = __expf(sacc[j][2] - mn1);
            float e3 = __expf(sacc[j][3] - mn1);
            sacc[j][0] = e0; sacc[j][1] = e1; sacc[j][2] = e2; sacc[j][3] = e3;
            sum0 += e0 + e1; sum1 += e2 + e3;
        }
        sum0 += __shfl_xor_sync(0xffffffffu, sum0, 1);
        sum0 += __shfl_xor_sync(0xffffffffu, sum0, 2);
        sum1 += __shfl_xor_sync(0xffffffffu, sum1, 1);
        sum1 += __shfl_xor_sync(0xffffffffu, sum1, 2);

        float c0 = __expf(mrun0 - mn0), c1 = __expf(mrun1 - mn1);
        lrun0 = lrun0 * c0 + sum0;
        lrun1 = lrun1 * c1 + sum1;
        mrun0 = mn0; mrun1 = mn1;
#pragma unroll
        for (int j = 0; j < 16; j++) {
            oacc[j][0] *= c0; oacc[j][1] *= c0;
            oacc[j][2] *= c1; oacc[j][3] *= c1;
        }

        // ---- O += P V (single-pass fp16, 64 keys in 4 chunks) -----------------
#pragma unroll
        for (int kc = 0; kc < 4; kc++) {
            uint32_t pa[4];
            __half2 p0 = __floats2half2_rn(sacc[2*kc][0],   sacc[2*kc][1]);
            __half2 p1 = __floats2half2_rn(sacc[2*kc][2],   sacc[2*kc][3]);
            __half2 p2 = __floats2half2_rn(sacc[2*kc+1][0], sacc[2*kc+1][1]);
            __half2 p3 = __floats2half2_rn(sacc[2*kc+1][2], sacc[2*kc+1][3]);
            pa[0] = *(uint32_t*)&p0; pa[1] = *(uint32_t*)&p1;
            pa[2] = *(uint32_t*)&p2; pa[3] = *(uint32_t*)&p3;
#pragma unroll
            for (int nd = 0; nd < 8; nd++) {
                uint32_t rv = base + TB + (uint32_t)(kc * 16 + vrow) * KROW
                              + ((uint32_t)(nd * 16 + vcoff) << 1);
                uint32_t vh4[4];
                ldm_x4_t(vh4, rv);
#pragma unroll
                for (int ia = 0; ia < 2; ia++)
                    mma_f16(oacc[nd * 2 + ia], pa, vh4[2 * ia], vh4[2 * ia + 1]);
            }
        }
        __syncthreads();
    }

    // ---- epilogue: normalize, write single fp16 for the Wo GEMM ----------------
    const float inv0 = 1.0f / lrun0, inv1 = 1.0f / lrun1;
    const size_t r0 = (size_t)(b * SS + q0 + wm + (lane >> 2)) * (NH * DH)
                      + h * DH + ((lane & 3) << 1);
    const size_t r1 = r0 + (size_t)8 * (NH * DH);
#pragma unroll
    for (int nd = 0; nd < 16; nd++) {
        __half2 h0 = __floats2half2_rn(oacc[nd][0] * inv0, oacc[nd][1] * inv0);
        __half2 h1 = __floats2half2_rn(oacc[nd][2] * inv1, oacc[nd][3] * inv1);
        *(__half2*)(g_att16 + r0 + nd * 8) = h0;
        *(__half2*)(g_att16 + r1 + nd * 8) = h1;
    }
}

// ---------------- launch --------------------------------------------------------
extern "C" void kernel_launch(void* const* d_in, const int* in_sizes, int n_in,
                              void* d_out, int out_size)
{
    const float* x   = (const float*)d_in[0];
    // d_in[1] = mask (causal; handled analytically)
    const int*   pos = (const int*)d_in[2];
    const float* Wq  = (const float*)d_in[3];
    const float* Wk  = (const float*)d_in[4];
    const float* Wv  = (const float*)d_in[5];
    const float* Wo  = (const float*)d_in[6];
    float* out = (float*)d_out;

    __half *qkv16i, *x16, *wqkv, *wo, *att16;
    cudaGetSymbolAddress((void**)&qkv16i, g_qkv16i);
    cudaGetSymbolAddress((void**)&x16,    g_x16);
    cudaGetSymbolAddress((void**)&wqkv,   g_wqkv16);
    cudaGetSymbolAddress((void**)&wo,     g_wo16);
    cudaGetSymbolAddress((void**)&att16,  g_att16);

    cudaFuncSetAttribute(attn_kernel,
                         cudaFuncAttributeMaxDynamicSharedMemorySize, AT_SMEM);
    cudaFuncSetAttribute(mm_f16_kernel<float>,
                         cudaFuncAttributeMaxDynamicSharedMemorySize, MM_SMEM);
    cudaFuncSetAttribute(mm_f16_kernel<__half>,
                         cudaFuncAttributeMaxDynamicSharedMemorySize, MM_SMEM);

    // convert x to fp16; transpose+convert all weights in ONE launch
    cvt16_kernel<<<(MROWS * DIM / 4 + 255) / 256, 256>>>(x, x16, MROWS * DIM / 4);
    cvtT16_all_kernel<<<dim3(DIM / 32, DIM / 32, 4), dim3(32, 8)>>>(Wq, Wk, Wv, Wo);

    // fused QKV projection (fp16 single-pass, fp16 output)
    mm_f16_kernel<__half><<<dim3(NQKV / 128, MROWS / 128), 128, MM_SMEM>>>(
        x16, wqkv, qkv16i, NQKV);

    // RoPE -> fp16 attention operands
    rope_kernel<<<dim3(SS, BB), 256>>>(pos);

    // attention (fp16 single-pass, 64x64 tiles, 3 CTAs/SM co-resident)
    attn_kernel<<<dim3(SS / AQM, NH, BB), 128, AT_SMEM>>>();

    // output projection (fp16 single-pass, fp32 output)
    mm_f16_kernel<float><<<dim3(DIM / 128, MROWS / 128), 128, MM_SMEM>>>(
        att16, wo, out, DIM);
}

// round 16
// speedup vs baseline: 1.0635x; 1.0038x over previous
#include <cuda_runtime.h>
#include <cuda_bf16.h>
#include <cuda_fp16.h>
#include <math.h>
#include <stdint.h>

// Problem constants
#define BB 2
#define SS 2048
#define DIM 2048
#define NH 16
#define KVH 4
#define DH 128
#define MROWS (BB * SS)   // 4096
#define NQKV 3072         // fused QKV output width (2048 q + 512 k + 512 v)

// ---------------- scratch (device globals; no allocation allowed) -------------
__device__ __half g_qkv16i[MROWS * NQKV];       // fused QKV projection output (fp16)

// attention operands (fp16), layout [b,h,s,d]
__device__ __half g_q16[BB * NH * SS * DH];     // Q (scale folded)
__device__ __half g_k16[BB * KVH * SS * DH];    // K
__device__ __half g_v16[BB * KVH * SS * DH];    // V

// fp16 GEMM operands
__device__ __half g_x16[MROWS * DIM];           // x
__device__ __half g_wqkv16[NQKV * DIM];         // fused W_qkv, transposed [N][K]
__device__ __half g_wo16[DIM * DIM];            // W_o, transposed [N][K]
__device__ __half g_att16[MROWS * (NH*DH)];     // attention output

// ---------------- PTX helpers ---------------------------------------------------
__device__ __forceinline__ uint32_t smem_u32(const void* p) {
    uint32_t a;
    asm("{ .reg .u64 t; cvta.to.shared.u64 t, %1; cvt.u32.u64 %0, t; }"
        : "=r"(a) : "l"(p));
    return a;
}

__device__ __forceinline__ void cp16(uint32_t dst, const void* src) {
    asm volatile("cp.async.cg.shared.global [%0], [%1], 16;\n"
                 :: "r"(dst), "l"(src));
}

__device__ __forceinline__ void ldm_x4(uint32_t r[4], uint32_t addr) {
    asm volatile("ldmatrix.sync.aligned.m8n8.x4.shared.b16 {%0,%1,%2,%3}, [%4];"
                 : "=r"(r[0]), "=r"(r[1]), "=r"(r[2]), "=r"(r[3]) : "r"(addr));
}

__device__ __forceinline__ void ldm_x4_t(uint32_t r[4], uint32_t addr) {
    asm volatile("ldmatrix.sync.aligned.m8n8.x4.trans.shared.b16 {%0,%1,%2,%3}, [%4];"
                 : "=r"(r[0]), "=r"(r[1]), "=r"(r[2]), "=r"(r[3]) : "r"(addr));
}

__device__ __forceinline__ void mma_f16(float c[4], const uint32_t a[4],
                                        uint32_t b0, uint32_t b1) {
    asm volatile(
        "mma.sync.aligned.m16n8k16.row.col.f32.f16.f16.f32 "
        "{%0,%1,%2,%3}, {%4,%5,%6,%7}, {%8,%9}, {%0,%1,%2,%3};"
        : "+f"(c[0]), "+f"(c[1]), "+f"(c[2]), "+f"(c[3])
        : "r"(a[0]), "r"(a[1]), "r"(a[2]), "r"(a[3]), "r"(b0), "r"(b1));
}

// ---------------- fp32 -> fp16 single convert ----------------------------------
__global__ __launch_bounds__(256) void cvt16_kernel(
    const float* __restrict__ in, __half* __restrict__ out, int n4)
{
    int i = blockIdx.x * blockDim.x + threadIdx.x;
    if (i >= n4) return;
    float4 v = ((const float4*)in)[i];
    __half2 a = __floats2half2_rn(v.x, v.y);
    __half2 b = __floats2half2_rn(v.z, v.w);
    ((__half2*)out)[2*i]   = a;
    ((__half2*)out)[2*i+1] = b;
}

// ---------------- all weights: fp32 [K][N] -> fp16 transposed [N][K], one launch -
__global__ __launch_bounds__(256) void cvtT16_all_kernel(
    const float* __restrict__ Wq, const float* __restrict__ Wk,
    const float* __restrict__ Wv, const float* __restrict__ Wo)
{
    const int z = blockIdx.z;
    const float* W;
    __half* T;
    int N;
    if (z == 0)      { W = Wq; T = g_wqkv16;                        N = DIM; }
    else if (z == 1) { W = Wk; T = g_wqkv16 + (size_t)2048 * DIM;   N = KVH * DH; }
    else if (z == 2) { W = Wv; T = g_wqkv16 + (size_t)2560 * DIM;   N = KVH * DH; }
    else             { W = Wo; T = g_wo16;                          N = DIM; }
    if (blockIdx.x * 32 >= N) return;

    __shared__ float t[32][33];
    const int n0 = blockIdx.x * 32, k0 = blockIdx.y * 32;
    const int tx = threadIdx.x, ty = threadIdx.y;   // (32, 8)
    for (int i = ty; i < 32; i += 8)
        t[i][tx] = W[(size_t)(k0 + i) * N + n0 + tx];
    __syncthreads();
    for (int i = ty; i < 32; i += 8)
        T[(size_t)(n0 + i) * DIM + k0 + tx] = __float2half_rn(t[tx][i]);
}

// ---------------- fp16 mma.sync single-pass GEMM --------------------------------
// C[M,N] = A @ B^T.  A:[M][K] fp16, B:[N][K] fp16. OutT = float or __half.
// CTA 128x64, 4 warps (warp tile 64x32), BK=32, double-buffered cp.async.
// Finer N-tiles halve the wave-quantization tail vs 128x128.
#define GK 2048
#define ROWB 80
#define TILE_A (128 * ROWB)       // 10240
#define TILE_BB (64 * ROWB)       // 5120
#define OFF_A  0
#define OFF_B  TILE_A
#define STG (TILE_A + TILE_BB)    // 15360
#define MM_SMEM (2 * STG)         // 30720

template <typename OutT>
__global__ __launch_bounds__(128) void mm_f16_kernel(
    const __half* __restrict__ A, const __half* __restrict__ B,
    OutT* __restrict__ C, int N)
{
    extern __shared__ char smem[];
    const uint32_t sb = smem_u32(smem);
    const int tid = threadIdx.x;
    const int lane = tid & 31, warp = tid >> 5;
    const int m0 = blockIdx.y * 128, n0 = blockIdx.x * 64;
    const int wm0 = (warp >> 1) * 64;     // 2x2 warp grid, warp tile 64x32
    const int wn0 = (warp & 1) * 32;

    const int arow_l  = lane & 15;
    const int akoff_l = (lane >> 4) << 3;
    const int brow_l  = (lane & 7) + ((lane >> 4) << 3);
    const int bkoff_l = ((lane >> 3) & 1) << 3;

    float acc[4][4][4];
#pragma unroll
    for (int im = 0; im < 4; im++)
#pragma unroll
        for (int j = 0; j < 4; j++)
#pragma unroll
            for (int c = 0; c < 4; c++) acc[im][j][c] = 0.0f;

    const int NT = GK / 32;

    auto issue = [&](int t) {
        const int k0 = t * 32;
        const uint32_t sbase = sb + (t & 1) * STG;
#pragma unroll
        for (int i = 0; i < 4; i++) {           // A: 128 rows x 4 chunks
            const int c = tid + (i << 7);
            const int row = c >> 2;
            const int off = (c & 3) << 3;
            cp16(sbase + OFF_A + (uint32_t)row * ROWB + ((uint32_t)off << 1),
                 A + (size_t)(m0 + row) * GK + k0 + off);
        }
#pragma unroll
        for (int i = 0; i < 2; i++) {           // B: 64 rows x 4 chunks
            const int c = tid + (i << 7);
            const int row = c >> 2;
            const int off = (c & 3) << 3;
            cp16(sbase + OFF_B + (uint32_t)row * ROWB + ((uint32_t)off << 1),
                 B + (size_t)(n0 + row) * GK + k0 + off);
        }
        asm volatile("cp.async.commit_group;");
    };

    issue(0);

    for (int t = 0; t < NT; t++) {
        if (t + 1 < NT) issue(t + 1);
        if (t + 1 < NT) { asm volatile("cp.async.wait_group 1;"); }
        else            { asm volatile("cp.async.wait_group 0;"); }
        __syncthreads();

        const uint32_t sbase = sb + (t & 1) * STG;
#pragma unroll
        for (int ks = 0; ks < 2; ks++) {
            uint32_t ah[4][4];
            const uint32_t kba = (uint32_t)(ks * 16 + akoff_l) << 1;
#pragma unroll
            for (int im = 0; im < 4; im++) {
                uint32_t ra = sbase + OFF_A
                            + (uint32_t)(wm0 + im * 16 + arow_l) * ROWB + kba;
                ldm_x4(ah[im], ra);
            }
            const uint32_t kbb = (uint32_t)(ks * 16 + bkoff_l) << 1;
#pragma unroll
            for (int np = 0; np < 2; np++) {
                uint32_t rb = sbase + OFF_B
                            + (uint32_t)(wn0 + np * 16 + brow_l) * ROWB + kbb;
                uint32_t bh[4];
                ldm_x4(bh, rb);
#pragma unroll
                for (int im = 0; im < 4; im++) {
#pragma unroll
                    for (int ia = 0; ia < 2; ia++)
                        mma_f16(acc[im][np * 2 + ia], ah[im],
                                bh[2 * ia], bh[2 * ia + 1]);
                }
            }
        }
        __syncthreads();
    }

#pragma unroll
    for (int im = 0; im < 4; im++) {
        const int rbase = m0 + wm0 + im * 16 + (lane >> 2);
#pragma unroll
        for (int j = 0; j < 4; j++) {
            const int col = n0 + wn0 + j * 8 + (lane & 3) * 2;
            if constexpr (sizeof(OutT) == 4) {
                float2 v0 = make_float2(acc[im][j][0], acc[im][j][1]);
                float2 v1 = make_float2(acc[im][j][2], acc[im][j][3]);
                *(float2*)((float*)C + (size_t)rbase * N + col)       = v0;
                *(float2*)((float*)C + (size_t)(rbase + 8) * N + col) = v1;
            } else {
                __half2 v0 = __floats2half2_rn(acc[im][j][0], acc[im][j][1]);
                __half2 v1 = __floats2half2_rn(acc[im][j][2], acc[im][j][3]);
                *(__half2*)((__half*)C + (size_t)rbase * N + col)       = v0;
                *(__half2*)((__half*)C + (size_t)(rbase + 8) * N + col) = v1;
            }
        }
    }
}

// ---------------- RoPE (fp16 in) -> fp16 attention operands [b,h,s,d] -----------
// Vectorized: __half2 loads/stores over (i, i+1) pairs.
__global__ __launch_bounds__(256) void rope_kernel(const int* __restrict__ pos_ids)
{
    const int s = blockIdx.x;
    const int b = blockIdx.y;
    const int t = threadIdx.x;

    __shared__ float cs[64], sn[64];
    if (t < 64) {
        double invf = exp(-((double)(2 * t) / (double)DH) * log(10000.0));
        double ang = (double)pos_ids[s] * invf;
        cs[t] = (float)cos(ang);
        sn[t] = (float)sin(ang);
    }
    __syncthreads();

    const float qk_scale = 0.08838834764831845f;   // 1/sqrt(128), folded into Q
    const __half* row = g_qkv16i + (size_t)(b * SS + s) * NQKV;

    // Q: rotate + scale (pairs)
    for (int idx = t; idx < NH * 32; idx += 256) {
        int h = idx >> 5, i = (idx & 31) * 2;
        __half2 a = *(const __half2*)(row + h * DH + i);
        __half2 c = *(const __half2*)(row + h * DH + 64 + i);
        float x1a = __low2float(a), x1b = __high2float(a);
        float x2a = __low2float(c), x2b = __high2float(c);
        float c0 = cs[i], c1 = cs[i + 1], s0 = sn[i], s1 = sn[i + 1];
        size_t dst = ((size_t)(b * NH + h) * SS + s) * DH;
        *(__half2*)(g_q16 + dst + i) =
            __floats2half2_rn((x1a * c0 - x2a * s0) * qk_scale,
                              (x1b * c1 - x2b * s1) * qk_scale);
        *(__half2*)(g_q16 + dst + 64 + i) =
            __floats2half2_rn((x2a * c0 + x1a * s0) * qk_scale,
                              (x2b * c1 + x1b * s1) * qk_scale);
    }

    // K: rotate (pairs)
    const __half* krow = row + 2048;
    for (int idx = t; idx < KVH * 32; idx += 256) {
        int h = idx >> 5, i = (idx & 31) * 2;
        __half2 a = *(const __half2*)(krow + h * DH + i);
        __half2 c = *(const __half2*)(krow + h * DH + 64 + i);
        float x1a = __low2float(a), x1b = __high2float(a);
        float x2a = __low2float(c), x2b = __high2float(c);
        float c0 = cs[i], c1 = cs[i + 1], s0 = sn[i], s1 = sn[i + 1];
        size_t dst = ((size_t)(b * KVH + h) * SS + s) * DH;
        *(__half2*)(g_k16 + dst + i) =
            __floats2half2_rn(x1a * c0 - x2a * s0, x1b * c1 - x2b * s1);
        *(__half2*)(g_k16 + dst + 64 + i) =
            __floats2half2_rn(x2a * c0 + x1a * s0, x2b * c1 + x1b * s1);
    }

    // V: relayout copy (vectorized)
    const __half* vrow = row + 2560;
    for (int idx = t; idx < KVH * DH / 2; idx += 256) {
        int h = idx >> 6, d2 = idx & 63;
        __half2 v = *(const __half2*)(vrow + h * DH + d2 * 2);
        *(__half2*)(g_v16 + ((size_t)(b * KVH + h) * SS + s) * DH + d2 * 2) = v;
    }
}

// ---------------- flash attention (fp16 mma.sync, causal, GQA) ------------------
// CTA: 64 q rows x 64-key blocks, 4 warps x 16 q rows, 128 threads.
#define AQM 64
#define AKN 64
#define KROW 272                  // smem row stride bytes (256 data + 16 pad)
#define TB (AKN * KROW)           // 17408
#define AT_SMEM (4 * TB)          // 69632: 2 stages x (K, V)

__global__ __launch_bounds__(128) void attn_kernel()
{
    extern __shared__ char smc[];
    const uint32_t sb = smem_u32(smc);
    const int tid = threadIdx.x, lane = tid & 31, warp = tid >> 5;
    const int qt = (int)gridDim.x - 1 - (int)blockIdx.x;   // heavy tiles first
    const int h = blockIdx.y, b = blockIdx.z, kvh = h >> 2;
    const int q0 = qt * AQM;
    const int wm = warp * 16;

    const char* qp = (const char*)(g_q16 + ((size_t)(b * NH + h) * SS + q0) * DH);
    const char* kp = (const char*)(g_k16 + (size_t)(b * KVH + kvh) * SS * DH);
    const char* vp = (const char*)(g_v16 + (size_t)(b * KVH + kvh) * SS * DH);

    // ---- stage Q (64x128 fp16) into smem, ldmatrix to registers ---------------
    for (int i = tid; i < AQM * 16; i += 128) {
        int row = i >> 4, ch = (i & 15) << 4;
        cp16(sb + (uint32_t)row * KROW + ch, qp + row * 256 + ch);
    }
    asm volatile("cp.async.commit_group;");
    asm volatile("cp.async.wait_group 0;");
    __syncthreads();

    const int arow = lane & 15, akoff = (lane >> 4) << 3;
    uint32_t qf[8][4];
#pragma unroll
    for (int kc = 0; kc < 8; kc++) {
        uint32_t ra = sb + (uint32_t)(wm + arow) * KROW + ((uint32_t)(kc * 16 + akoff) << 1);
        ldm_x4(qf[kc], ra);
    }
    __syncthreads();   // staging area free for K/V now

    float oacc[16][4];
#pragma unroll
    for (int j = 0; j < 16; j++)
#pragma unroll
        for (int c = 0; c < 4; c++) oacc[j][c] = 0.0f;
    float mrun0 = -INFINITY, mrun1 = -INFINITY;
    float lrun0 = 0.0f, lrun1 = 0.0f;

    const int nblocks = qt + 1;
    const int brow = (lane & 7) + ((lane >> 4) << 3);
    const int bkoff = ((lane >> 3) & 1) << 3;
    const int vrow = lane & 15, vcoff = (lane >> 4) << 3;

    auto issue = [&](int t) {
        const uint32_t base = sb + (uint32_t)(t & 1) * (2 * TB);
        const size_t g0 = (size_t)t * AKN * 256;
        for (int i = tid; i < AKN * 16; i += 128) {
            int row = i >> 4, ch = (i & 15) << 4;
            uint32_t soff = (uint32_t)row * KROW + ch;
            size_t goff = g0 + (size_t)row * 256 + ch;
            cp16(base + soff,      kp + goff);
            cp16(base + TB + soff, vp + goff);
        }
        asm volatile("cp.async.commit_group;");
    };

    issue(0);

    for (int t = 0; t < nblocks; t++) {
        if (t + 1 < nblocks) { issue(t + 1); asm volatile("cp.async.wait_group 1;"); }
        else                 { asm volatile("cp.async.wait_group 0;"); }
        __syncthreads();
        const uint32_t base = sb + (uint32_t)(t & 1) * (2 * TB);

        // ---- S = Q K^T (single-pass fp16, 16x64 per warp) ---------------------
        float sacc[8][4];
#pragma unroll
        for (int j = 0; j < 8; j++)
#pragma unroll
            for (int c = 0; c < 4; c++) sacc[j][c] = 0.0f;

#pragma unroll
        for (int kc = 0; kc < 8; kc++) {
            const uint32_t kb = (uint32_t)(kc * 16 + bkoff) << 1;
#pragma unroll
            for (int np = 0; np < 4; np++) {
                uint32_t rb = base + (uint32_t)(np * 16 + brow) * KROW + kb;
                uint32_t bh4[4];
                ldm_x4(bh4, rb);
#pragma unroll
                for (int ia = 0; ia < 2; ia++)
                    mma_f16(sacc[np * 2 + ia], qf[kc], bh4[2 * ia], bh4[2 * ia + 1]);
            }
        }

        // ---- causal mask (warp-uniform skip when fully unmasked) --------------
        const int k0 = t * AKN;
        if (k0 + AKN - 1 > q0 + wm) {
            const int r0 = q0 + wm + (lane >> 2);
#pragma unroll
            for (int j = 0; j < 8; j++) {
                int cb = k0 + j * 8 + ((lane & 3) << 1);
                if (cb     > r0)     sacc[j][0] = -INFINITY;
                if (cb + 1 > r0)     sacc[j][1] = -INFINITY;
                if (cb     > r0 + 8) sacc[j][2] = -INFINITY;
                if (cb + 1 > r0 + 8) sacc[j][3] = -INFINITY;
            }
        }

        // ---- online softmax ---------------------------------------------------
        float mx0 = -INFINITY, mx1 = -INFINITY;
#pragma unroll
        for (int j = 0; j < 8; j++) {
            mx0 = fmaxf(mx0, fmaxf(sacc[j][0], sacc[j][1]));
            mx1 = fmaxf(mx1, fmaxf(sacc[j][2], sacc[j][3]));
        }
        mx0 = fmaxf(mx0, __shfl_xor_sync(0xffffffffu, mx0, 1));
        mx0 = fmaxf(mx0, __shfl_xor_sync(0xffffffffu, mx0, 2));
        mx1 = fmaxf(mx1, __shfl_xor_sync(0xffffffffu, mx1, 1));
        mx1 = fmaxf(mx1, __shfl_xor_sync(0xffffffffu, mx1, 2));
        float mn0 = fmaxf(mrun0, mx0), mn1 = fmaxf(mrun1, mx1);

        float sum0 = 0.0f, sum1 = 0.0f;
#pragma unroll
        for (int j = 0; j < 8; j++) {
            float e0 = __expf(sacc[j][0] - mn0);
            float e1 = __expf(sacc[j][1] - mn0);
            float e2 = __expf(sacc[j][2] - mn1);
            float e3 = __expf(sacc[j][3] - mn1);
            sacc[j][0] = e0; sacc[j][1] = e1; sacc[j][2] = e2; sacc[j][3] = e3;
            sum0 += e0 + e1; sum1 += e2 + e3;
        }
        sum0 += __shfl_xor_sync(0xffffffffu, sum0, 1);
        sum0 += __shfl_xor_sync(0xffffffffu, sum0, 2);
        sum1 += __shfl_xor_sync(0xffffffffu, sum1, 1);
        sum1 += __shfl_xor_sync(0xffffffffu, sum1, 2);

        float c0 = __expf(mrun0 - mn0), c1 = __expf(mrun1 - mn1);
        lrun0 = lrun0 * c0 + sum0;
        lrun1 = lrun1 * c1 + sum1;
        mrun0 = mn0; mrun1 = mn1;
#pragma unroll
        for (int j = 0; j < 16; j++) {
            oacc[j][0] *= c0; oacc[j][1] *= c0;
            oacc[j][2] *= c1; oacc[j][3] *= c1;
        }

        // ---- O += P V (single-pass fp16, 64 keys in 4 chunks) -----------------
#pragma unroll
        for (int kc = 0; kc < 4; kc++) {
            uint32_t pa[4];
            __half2 p0 = __floats2half2_rn(sacc[2*kc][0],   sacc[2*kc][1]);
            __half2 p1 = __floats2half2_rn(sacc[2*kc][2],   sacc[2*kc][3]);
            __half2 p2 = __floats2half2_rn(sacc[2*kc+1][0], sacc[2*kc+1][1]);
            __half2 p3 = __floats2half2_rn(sacc[2*kc+1][2], sacc[2*kc+1][3]);
            pa[0] = *(uint32_t*)&p0; pa[1] = *(uint32_t*)&p1;
            pa[2] = *(uint32_t*)&p2; pa[3] = *(uint32_t*)&p3;
#pragma unroll
            for (int nd = 0; nd < 8; nd++) {
                uint32_t rv = base + TB + (uint32_t)(kc * 16 + vrow) * KROW
                              + ((uint32_t)(nd * 16 + vcoff) << 1);
                uint32_t vh4[4];
                ldm_x4_t(vh4, rv);
#pragma unroll
                for (int ia = 0; ia < 2; ia++)
                    mma_f16(oacc[nd * 2 + ia], pa, vh4[2 * ia], vh4[2 * ia + 1]);
            }
        }
        __syncthreads();
    }

    // ---- epilogue: normalize, write single fp16 for the Wo GEMM ----------------
    const float inv0 = 1.0f / lrun0, inv1 = 1.0f / lrun1;
    const size_t r0 = (size_t)(b * SS + q0 + wm + (lane >> 2)) * (NH * DH)
                      + h * DH + ((lane & 3) << 1);
    const size_t r1 = r0 + (size_t)8 * (NH * DH);
#pragma unroll
    for (int nd = 0; nd < 16; nd++) {
        __half2 h0 = __floats2half2_rn(oacc[nd][0] * inv0, oacc[nd][1] * inv0);
        __half2 h1 = __floats2half2_rn(oacc[nd][2] * inv1, oacc[nd][3] * inv1);
        *(__half2*)(g_att16 + r0 + nd * 8) = h0;
        *(__half2*)(g_att16 + r1 + nd * 8) = h1;
    }
}

// ---------------- launch --------------------------------------------------------
extern "C" void kernel_launch(void* const* d_in, const int* in_sizes, int n_in,
                              void* d_out, int out_size)
{
    const float* x   = (const float*)d_in[0];
    // d_in[1] = mask (causal; handled analytically)
    const int*   pos = (const int*)d_in[2];
    const float* Wq  = (const float*)d_in[3];
    const float* Wk  = (const float*)d_in[4];
    const float* Wv  = (const float*)d_in[5];
    const float* Wo  = (const float*)d_in[6];
    float* out = (float*)d_out;

    __half *qkv16i, *x16, *wqkv, *wo, *att16;
    cudaGetSymbolAddress((void**)&qkv16i, g_qkv16i);
    cudaGetSymbolAddress((void**)&x16,    g_x16);
    cudaGetSymbolAddress((void**)&wqkv,   g_wqkv16);
    cudaGetSymbolAddress((void**)&wo,     g_wo16);
    cudaGetSymbolAddress((void**)&att16,  g_att16);

    cudaFuncSetAttribute(attn_kernel,
                         cudaFuncAttributeMaxDynamicSharedMemorySize, AT_SMEM);
    cudaFuncSetAttribute(mm_f16_kernel<float>,
                         cudaFuncAttributeMaxDynamicSharedMemorySize, MM_SMEM);
    cudaFuncSetAttribute(mm_f16_kernel<__half>,
                         cudaFuncAttributeMaxDynamicSharedMemorySize, MM_SMEM);

    // convert x to fp16; transpose+convert all weights in ONE launch
    cvt16_kernel<<<(MROWS * DIM / 4 + 255) / 256, 256>>>(x, x16, MROWS * DIM / 4);
    cvtT16_all_kernel<<<dim3(DIM / 32, DIM / 32, 4), dim3(32, 8)>>>(Wq, Wk, Wv, Wo);

    // fused QKV projection (fp16 single-pass, fp16 output, 128x64 tiles)
    mm_f16_kernel<__half><<<dim3(NQKV / 64, MROWS / 128), 128, MM_SMEM>>>(
        x16, wqkv, qkv16i, NQKV);

    // RoPE -> fp16 attention operands (vectorized)
    rope_kernel<<<dim3(SS, BB), 256>>>(pos);

    // attention (fp16 single-pass, 64x64 tiles)
    attn_kernel<<<dim3(SS / AQM, NH, BB), 128, AT_SMEM>>>();

    // output projection (fp16 single-pass, fp32 output, 128x64 tiles)
    mm_f16_kernel<float><<<dim3(DIM / 64, MROWS / 128), 128, MM_SMEM>>>(
        att16, wo, out, DIM);
}